// round 10
// baseline (speedup 1.0000x reference)
#include <cuda_runtime.h>

#define Bc 4
#define Sc 1024
#define Dc 512
#define Hc 8
#define DHc 64

typedef unsigned long long u64;

// ---- f32x2 packed-math helpers (FFMA2 path: ptxas only emits via PTX) ----
__device__ __forceinline__ u64 ffma2(u64 a, u64 b, u64 c) {
    u64 d;
    asm("fma.rn.f32x2 %0, %1, %2, %3;" : "=l"(d) : "l"(a), "l"(b), "l"(c));
    return d;
}
__device__ __forceinline__ u64 fmul2(u64 a, u64 b) {
    u64 d;
    asm("mul.rn.f32x2 %0, %1, %2;" : "=l"(d) : "l"(a), "l"(b));
    return d;
}
__device__ __forceinline__ u64 pack2(float lo, float hi) {
    u64 d;
    asm("mov.b64 %0, {%1, %2};" : "=l"(d)
        : "r"(__float_as_uint(lo)), "r"(__float_as_uint(hi)));
    return d;
}
__device__ __forceinline__ u64 dup2(float x) { return pack2(x, x); }
__device__ __forceinline__ float2 unpk2(u64 v) {
    unsigned lo, hi;
    asm("mov.b64 {%0, %1}, %2;" : "=r"(lo), "=r"(hi) : "l"(v));
    return make_float2(__uint_as_float(lo), __uint_as_float(hi));
}

// ---- scratch (no allocations allowed) ----
__device__ float g_Q[Bc*Hc*Sc*DHc];   // [B,H,S,DH]
__device__ float g_K[Bc*Hc*Sc*DHc];
__device__ float g_V[Bc*Hc*Sc*DHc];
__device__ float g_ctx[Bc*Sc*Dc];     // [B,S,D]

// ============================================================
// GEMM: out = A[M,512] @ W[512,512]
// 128x128 block tile, 512 threads, 8(m)x4(n) per thread,
// f32x2 accumulators, double-buffered smem + register prefetch
// (one __syncthreads per k-step; next tile's global loads fly
// under the current tile's FFMA2 work).
// ============================================================
__device__ __forceinline__ void gemm_body(const float* __restrict__ A,
                                          const float* __restrict__ W,
                                          float* __restrict__ out,
                                          int headsplit) {
    __shared__ float As[2][16][132];   // [buf][k][m] transposed
    __shared__ float Bs[2][16][132];   // [buf][k][n]
    const int tid = threadIdx.x;
    const int tx = tid & 31;        // n-group (cols tx*4..tx*4+3)
    const int ty = tid >> 5;        // m-group (rows ty*8..ty*8+7)
    const int m0 = blockIdx.y << 7, n0 = blockIdx.x << 7;

    const int ar = tid >> 2;            // 0..127 (A row)
    const int ac = (tid & 3) << 2;      // 0,4,8,12 (A col in k-slice)
    const int br = tid >> 5;            // 0..15  (B row = k)
    const int bc = (tid & 31) << 2;     // 0..124 (B col)

    const float* Ap = A + (size_t)(m0 + ar) * 512 + ac;
    const float* Wp = W + (size_t)br * 512 + n0 + bc;

    u64 acc[4][4];
#pragma unroll
    for (int i = 0; i < 4; i++)
#pragma unroll
        for (int j = 0; j < 4; j++) acc[i][j] = 0ull;

    // prologue: fill buffer 0
    float4 av = *(const float4*)(Ap);
    float4 wv = *(const float4*)(Wp);
    As[0][ac+0][ar] = av.x; As[0][ac+1][ar] = av.y;
    As[0][ac+2][ar] = av.z; As[0][ac+3][ar] = av.w;
    *(float4*)&Bs[0][br][bc] = wv;
    __syncthreads();

    int buf = 0;
#pragma unroll 1
    for (int k0 = 0; k0 < 512; k0 += 16) {
        const bool more = (k0 + 16 < 512);
        if (more) {   // prefetch next tile into registers (latency hidden)
            av = *(const float4*)(Ap + k0 + 16);
            wv = *(const float4*)(Wp + (size_t)(k0 + 16) * 512);
        }
#pragma unroll
        for (int kk = 0; kk < 16; kk++) {
            ulonglong2 a01 = *(ulonglong2*)&As[buf][kk][ty*8];
            ulonglong2 a23 = *(ulonglong2*)&As[buf][kk][ty*8 + 4];
            float4 bv = *(float4*)&Bs[buf][kk][tx*4];
            u64 a2[4] = { a01.x, a01.y, a23.x, a23.y };
            u64 b2[4] = { dup2(bv.x), dup2(bv.y), dup2(bv.z), dup2(bv.w) };
#pragma unroll
            for (int i = 0; i < 4; i++)
#pragma unroll
                for (int j = 0; j < 4; j++)
                    acc[i][j] = ffma2(a2[i], b2[j], acc[i][j]);
        }
        if (more) {   // stage next tile into the other buffer
            As[buf^1][ac+0][ar] = av.x; As[buf^1][ac+1][ar] = av.y;
            As[buf^1][ac+2][ar] = av.z; As[buf^1][ac+3][ar] = av.w;
            *(float4*)&Bs[buf^1][br][bc] = wv;
        }
        __syncthreads();
        buf ^= 1;
    }

    const int n = n0 + tx*4;
    if (headsplit) {
        const int hh = n >> 6;          // head index
        const int nc = n & 63;          // col within head
#pragma unroll
        for (int i = 0; i < 4; i++) {
            float2 c0 = unpk2(acc[i][0]), c1 = unpk2(acc[i][1]);
            float2 c2 = unpk2(acc[i][2]), c3 = unpk2(acc[i][3]);
            int m = m0 + ty*8 + 2*i;
            int bb = m >> 10, s = m & 1023;
            *(float4*)&out[((size_t)(bb*Hc + hh) * Sc + s) * DHc + nc] =
                make_float4(c0.x, c1.x, c2.x, c3.x);
            int m2 = m + 1, bb2 = m2 >> 10, s2 = m2 & 1023;
            *(float4*)&out[((size_t)(bb2*Hc + hh) * Sc + s2) * DHc + nc] =
                make_float4(c0.y, c1.y, c2.y, c3.y);
        }
    } else {
#pragma unroll
        for (int i = 0; i < 4; i++) {
            float2 c0 = unpk2(acc[i][0]), c1 = unpk2(acc[i][1]);
            float2 c2 = unpk2(acc[i][2]), c3 = unpk2(acc[i][3]);
            int m = m0 + ty*8 + 2*i;
            *(float4*)&out[(size_t)m * 512 + n] = make_float4(c0.x, c1.x, c2.x, c3.x);
            *(float4*)&out[(size_t)(m+1) * 512 + n] = make_float4(c0.y, c1.y, c2.y, c3.y);
        }
    }
}

// Merged 3-way projection: z selects (A, W, dst).
__global__ __launch_bounds__(512, 1) void proj3(const float* __restrict__ A0,
                                                const float* __restrict__ A1,
                                                const float* __restrict__ A2,
                                                const float* __restrict__ W0,
                                                const float* __restrict__ W1,
                                                const float* __restrict__ W2,
                                                float* __restrict__ O0,
                                                float* __restrict__ O1,
                                                float* __restrict__ O2) {
    const int z = blockIdx.z;
    const float* A = (z == 0) ? A0 : (z == 1) ? A1 : A2;
    const float* W = (z == 0) ? W0 : (z == 1) ? W1 : W2;
    float*       O = (z == 0) ? O0 : (z == 1) ? O1 : O2;
    gemm_body(A, W, O, 1);
}

__global__ __launch_bounds__(512, 1) void gemm512(const float* __restrict__ A,
                                                  const float* __restrict__ W,
                                                  float* __restrict__ out) {
    gemm_body(A, W, out, 0);
}

// ============================================================
// Fused causal attention with skewed relative bias (f32x2 math).
// bias[j,t] = sum_d q[j,d] * R[h][d][S-1-j+t]   (t <= j)
// smem aliasing: kv = K (QK phase) then V (PV phase);
//                rp = R window (QK phase), ps inside rp (PV phase).
// V tile prefetched into registers during the QK phase.
// ============================================================
__global__ __launch_bounds__(256, 3) void attn_kernel(const float* __restrict__ Rel) {
    extern __shared__ float sm[];
    float* qs = sm;                 // [d][j]  64x68   (persistent)
    float* kv = qs + 64*68;         // QK: K as [d][t] ; PV: V as [t][d]
    float* rp = kv + 64*68;         // QK: R as [d][cc] 64x128 ; PV: ps as [t][j]

    const int tid = threadIdx.x;
    const int tx = tid & 15, ty = tid >> 4;
    const int bh = blockIdx.y;
    const int h  = bh & (Hc-1);
    const int j0 = ((int)gridDim.x - 1 - (int)blockIdx.x) << 6;   // heavy first

    const float* Qp    = g_Q + ((size_t)bh * Sc + j0) * DHc;
    const float* Kbase = g_K + (size_t)bh * Sc * DHc;
    const float* Vbase = g_V + (size_t)bh * Sc * DHc;
    const float* Rp    = Rel + (size_t)h * DHc * Sc;

    // V prefetch addressing (same for every tile): thread covers 4 rows
    const int vt = tid >> 4;            // 0..15 base row
    const int vd4 = (tid & 15) << 2;    // 0..60

    for (int f = tid; f < 1024; f += 256) {
        int j = f >> 4, d4 = (f & 15) << 2;
        float4 v = *(const float4*)(Qp + j*DHc + d4);
        qs[(d4+0)*68 + j] = v.x; qs[(d4+1)*68 + j] = v.y;
        qs[(d4+2)*68 + j] = v.z; qs[(d4+3)*68 + j] = v.w;
    }

    float mrow[4] = {-1e30f, -1e30f, -1e30f, -1e30f};
    float lrow[4] = {0.f, 0.f, 0.f, 0.f};
    u64 oacc2[4][2];
#pragma unroll
    for (int i = 0; i < 4; i++) { oacc2[i][0] = 0ull; oacc2[i][1] = 0ull; }

    const int base0 = 60 + 4*tx - 4*ty;   // in [0,120], mult of 4
    const int ntiles = (j0 >> 6) + 1;

    for (int it = 0; it < ntiles; it++) {
        const int t0 = it << 6;
        __syncthreads();   // (a)

        for (int f = tid; f < 1024; f += 256) {
            int t = f >> 4, d4 = (f & 15) << 2;
            float4 k4 = *(const float4*)(Kbase + (size_t)(t0 + t)*DHc + d4);
            kv[(d4+0)*68 + t] = k4.x; kv[(d4+1)*68 + t] = k4.y;
            kv[(d4+2)*68 + t] = k4.z; kv[(d4+3)*68 + t] = k4.w;
        }
        const int cmin = Sc - 64 - j0 + t0;   // >= 0, multiple of 4
        for (int f = tid; f < 64*32; f += 256) {
            int d = f >> 5, cc4 = (f & 31) << 2;
            int col = cmin + cc4;
            float4 rv4 = (col < Sc) ? *(const float4*)(Rp + (size_t)d*Sc + col)
                                    : make_float4(0.f, 0.f, 0.f, 0.f);
            *(float4*)(rp + d*128 + cc4) = rv4;
        }
        __syncthreads();   // (b)

        // prefetch V tile into registers; flies under QK compute
        float4 vpre[4];
#pragma unroll
        for (int u = 0; u < 4; u++)
            vpre[u] = *(const float4*)(Vbase + (size_t)(t0 + vt + u*16)*DHc + vd4);

        // s[j][t] = q.k + q.R[:, S-1-j+t]  -- f32x2, pairs along t
        u64 acc2[4][2];
#pragma unroll
        for (int i = 0; i < 4; i++) { acc2[i][0] = 0ull; acc2[i][1] = 0ull; }
#pragma unroll 8
        for (int d = 0; d < 64; d++) {
            float4 qv = *(float4*)(qs + d*68 + ty*4);
            ulonglong2 kk2 = *(ulonglong2*)(kv + d*68 + tx*4);
            float4 r0 = *(float4*)(rp + d*128 + base0);
            float4 r1 = *(float4*)(rp + d*128 + base0 + 4);
            u64 qa2[4] = { dup2(qv.x), dup2(qv.y), dup2(qv.z), dup2(qv.w) };
            u64 e0 = pack2(r0.x, r0.y), e1 = pack2(r0.z, r0.w), e2 = pack2(r1.x, r1.y);
            u64 o1 = pack2(r0.y, r0.z), o3 = pack2(r0.w, r1.x), o5 = pack2(r1.y, r1.z);
            u64 rb00 = o3, rb01 = o5;   // i=0
            u64 rb10 = e1, rb11 = e2;   // i=1
            u64 rb20 = o1, rb21 = o3;   // i=2
            u64 rb30 = e0, rb31 = e1;   // i=3
            acc2[0][0] = ffma2(qa2[0], kk2.x, acc2[0][0]);
            acc2[0][1] = ffma2(qa2[0], kk2.y, acc2[0][1]);
            acc2[0][0] = ffma2(qa2[0], rb00,  acc2[0][0]);
            acc2[0][1] = ffma2(qa2[0], rb01,  acc2[0][1]);
            acc2[1][0] = ffma2(qa2[1], kk2.x, acc2[1][0]);
            acc2[1][1] = ffma2(qa2[1], kk2.y, acc2[1][1]);
            acc2[1][0] = ffma2(qa2[1], rb10,  acc2[1][0]);
            acc2[1][1] = ffma2(qa2[1], rb11,  acc2[1][1]);
            acc2[2][0] = ffma2(qa2[2], kk2.x, acc2[2][0]);
            acc2[2][1] = ffma2(qa2[2], kk2.y, acc2[2][1]);
            acc2[2][0] = ffma2(qa2[2], rb20,  acc2[2][0]);
            acc2[2][1] = ffma2(qa2[2], rb21,  acc2[2][1]);
            acc2[3][0] = ffma2(qa2[3], kk2.x, acc2[3][0]);
            acc2[3][1] = ffma2(qa2[3], kk2.y, acc2[3][1]);
            acc2[3][0] = ffma2(qa2[3], rb30,  acc2[3][0]);
            acc2[3][1] = ffma2(qa2[3], rb31,  acc2[3][1]);
        }

        float acc[4][4];
#pragma unroll
        for (int i = 0; i < 4; i++) {
            float2 u0 = unpk2(acc2[i][0]), u1 = unpk2(acc2[i][1]);
            acc[i][0] = u0.x; acc[i][1] = u0.y; acc[i][2] = u1.x; acc[i][3] = u1.y;
        }

        // online softmax (scale AFTER bias+mask, matching reference)
#pragma unroll
        for (int i = 0; i < 4; i++) {
            const int j = j0 + ty*4 + i;
            float mx = -1e30f;
#pragma unroll
            for (int c = 0; c < 4; c++) {
                int t = t0 + tx*4 + c;
                float v = (t <= j) ? acc[i][c] * 0.125f : -1e30f;
                acc[i][c] = v;
                mx = fmaxf(mx, v);
            }
#pragma unroll
            for (int off = 8; off; off >>= 1)
                mx = fmaxf(mx, __shfl_xor_sync(0xffffffffu, mx, off, 16));
            float mnew = fmaxf(mrow[i], mx);
            float corr = __expf(mrow[i] - mnew);
            float ss = 0.f;
#pragma unroll
            for (int c = 0; c < 4; c++) {
                float p = __expf(acc[i][c] - mnew);
                acc[i][c] = p;
                ss += p;
            }
#pragma unroll
            for (int off = 8; off; off >>= 1)
                ss += __shfl_xor_sync(0xffffffffu, ss, off, 16);
            lrow[i] = lrow[i] * corr + ss;
            mrow[i] = mnew;
            u64 corr2 = dup2(corr);
            oacc2[i][0] = fmul2(oacc2[i][0], corr2);
            oacc2[i][1] = fmul2(oacc2[i][1], corr2);
        }
        __syncthreads();   // (c)

        // store p transposed: ps[t][j] (inside rp); store prefetched V -> kv[t][d]
        float* ps = rp;
#pragma unroll
        for (int c = 0; c < 4; c++) {
            float4 pv = make_float4(acc[0][c], acc[1][c], acc[2][c], acc[3][c]);
            *(float4*)(ps + (tx*4 + c)*68 + ty*4) = pv;
        }
#pragma unroll
        for (int u = 0; u < 4; u++)
            *(float4*)(kv + (vt + u*16)*68 + vd4) = vpre[u];
        __syncthreads();   // (d)

        // O += P @ V  (f32x2, pairs along DH cols)
#pragma unroll 8
        for (int t = 0; t < 64; t++) {
            ulonglong2 vv2 = *(ulonglong2*)(kv + t*68 + tx*4);
            float4 p4 = *(float4*)(ps + t*68 + ty*4);
            u64 pa0 = dup2(p4.x), pa1 = dup2(p4.y), pa2v = dup2(p4.z), pa3 = dup2(p4.w);
            oacc2[0][0] = ffma2(pa0,  vv2.x, oacc2[0][0]);
            oacc2[0][1] = ffma2(pa0,  vv2.y, oacc2[0][1]);
            oacc2[1][0] = ffma2(pa1,  vv2.x, oacc2[1][0]);
            oacc2[1][1] = ffma2(pa1,  vv2.y, oacc2[1][1]);
            oacc2[2][0] = ffma2(pa2v, vv2.x, oacc2[2][0]);
            oacc2[2][1] = ffma2(pa2v, vv2.y, oacc2[2][1]);
            oacc2[3][0] = ffma2(pa3,  vv2.x, oacc2[3][0]);
            oacc2[3][1] = ffma2(pa3,  vv2.y, oacc2[3][1]);
        }
    }

    // epilogue: ctx[b][j][h*64 + dc]
    const int b = bh >> 3;
#pragma unroll
    for (int i = 0; i < 4; i++) {
        float inv = 1.f / lrow[i];
        float2 u0 = unpk2(oacc2[i][0]), u1 = unpk2(oacc2[i][1]);
        float4 o = make_float4(u0.x*inv, u0.y*inv, u1.x*inv, u1.y*inv);
        *(float4*)&g_ctx[((size_t)(b*Sc + j0 + ty*4 + i)) * Dc + h*DHc + tx*4] = o;
    }
}

// ============================================================
extern "C" void kernel_launch(void* const* d_in, const int* in_sizes, int n_in,
                              void* d_out, int out_size) {
    (void)in_sizes; (void)n_in; (void)out_size;
    const float* queries = (const float*)d_in[0];
    const float* keysp   = (const float*)d_in[1];
    const float* valuesp = (const float*)d_in[2];
    // d_in[3] = mask (causal; applied analytically)
    const float* Wq  = (const float*)d_in[4];
    const float* Wk  = (const float*)d_in[5];
    const float* Wv  = (const float*)d_in[6];
    const float* Wo  = (const float*)d_in[7];
    const float* rel = (const float*)d_in[8];
    float* out = (float*)d_out;

    float *pQ, *pK, *pV, *pC;
    cudaGetSymbolAddress((void**)&pQ, g_Q);
    cudaGetSymbolAddress((void**)&pK, g_K);
    cudaGetSymbolAddress((void**)&pV, g_V);
    cudaGetSymbolAddress((void**)&pC, g_ctx);

    // fused QKV projections: 128x128 tiles, z selects projection
    proj3<<<dim3(Dc/128, (Bc*Sc)/128, 3), 512>>>(queries, keysp, valuesp,
                                                 Wq, Wk, Wv, pQ, pK, pV);

    const int smem = (2*64*68 + 64*128) * (int)sizeof(float);   // 67584 B -> 3 CTAs/SM
    cudaFuncSetAttribute(attn_kernel, cudaFuncAttributeMaxDynamicSharedMemorySize, smem);
    attn_kernel<<<dim3(Sc/64, Bc*Hc), 256, smem>>>(rel);

    gemm512<<<dim3(Dc/128, (Bc*Sc)/128), 512>>>(pC, Wo, out);
}

// round 12
// speedup vs baseline: 1.5343x; 1.5343x over previous
#include <cuda_runtime.h>

#define Bc 4
#define Sc 1024
#define Dc 512
#define Hc 8
#define DHc 64

typedef unsigned long long u64;

// ---- f32x2 packed-math helpers (FFMA2 path: ptxas only emits via PTX) ----
__device__ __forceinline__ u64 ffma2(u64 a, u64 b, u64 c) {
    u64 d;
    asm("fma.rn.f32x2 %0, %1, %2, %3;" : "=l"(d) : "l"(a), "l"(b), "l"(c));
    return d;
}
__device__ __forceinline__ u64 fmul2(u64 a, u64 b) {
    u64 d;
    asm("mul.rn.f32x2 %0, %1, %2;" : "=l"(d) : "l"(a), "l"(b));
    return d;
}
__device__ __forceinline__ u64 pack2(float lo, float hi) {
    u64 d;
    asm("mov.b64 %0, {%1, %2};" : "=l"(d)
        : "r"(__float_as_uint(lo)), "r"(__float_as_uint(hi)));
    return d;
}
__device__ __forceinline__ u64 dup2(float x) { return pack2(x, x); }
__device__ __forceinline__ float2 unpk2(u64 v) {
    unsigned lo, hi;
    asm("mov.b64 {%0, %1}, %2;" : "=r"(lo), "=r"(hi) : "l"(v));
    return make_float2(__uint_as_float(lo), __uint_as_float(hi));
}

// ---- scratch (no allocations allowed) ----
__device__ float g_Q[Bc*Hc*Sc*DHc];   // [B,H,S,DH]
__device__ float g_K[Bc*Hc*Sc*DHc];
__device__ float g_V[Bc*Hc*Sc*DHc];
__device__ float g_ctx[Bc*Sc*Dc];     // [B,S,D]

// ============================================================
// GEMM: out = A[M,512] @ W[512,512]
// 128x64 block tile, 256 threads, 8(m)x4(n) per thread,
// f32x2 accumulators paired along M. Small CTA (13 KB smem,
// <=84 regs) -> 3 CTAs/SM so barrier/load latency overlaps
// ACROSS CTAs instead of via in-CTA pipelining (R10 lesson).
// ============================================================
__device__ __forceinline__ void gemm_body(const float* __restrict__ A,
                                          const float* __restrict__ W,
                                          float* __restrict__ out,
                                          int headsplit) {
    __shared__ float As[16][132];   // [k][m] transposed
    __shared__ float Bs[16][68];    // [k][n]
    const int tid = threadIdx.x;
    const int tx = tid & 15;        // n-group (cols tx*4..tx*4+3)
    const int ty = tid >> 4;        // m-group (rows ty*8..ty*8+7)
    const int m0 = blockIdx.y << 7, n0 = blockIdx.x << 6;

    const int ar = tid >> 1;            // 0..127 (A row)
    const int ac = (tid & 1) << 3;      // 0 or 8 (A col in k-slice)
    const int br = tid >> 4;            // 0..15  (B row = k)
    const int bc = (tid & 15) << 2;     // 0..60  (B col)

    u64 acc[4][4];                      // [m-pair][n]  (lo=row 2i, hi=row 2i+1)
#pragma unroll
    for (int i = 0; i < 4; i++)
#pragma unroll
        for (int j = 0; j < 4; j++) acc[i][j] = 0ull;

    for (int k0 = 0; k0 < 512; k0 += 16) {
        float4 a0 = *(const float4*)(A + (size_t)(m0 + ar) * 512 + k0 + ac);
        float4 a1 = *(const float4*)(A + (size_t)(m0 + ar) * 512 + k0 + ac + 4);
        As[ac+0][ar] = a0.x; As[ac+1][ar] = a0.y;
        As[ac+2][ar] = a0.z; As[ac+3][ar] = a0.w;
        As[ac+4][ar] = a1.x; As[ac+5][ar] = a1.y;
        As[ac+6][ar] = a1.z; As[ac+7][ar] = a1.w;
        float4 wv = *(const float4*)(W + (size_t)(k0 + br) * 512 + n0 + bc);
        *(float4*)&Bs[br][bc] = wv;
        __syncthreads();
#pragma unroll
        for (int kk = 0; kk < 16; kk++) {
            ulonglong2 a01 = *(ulonglong2*)&As[kk][ty*8];
            ulonglong2 a23 = *(ulonglong2*)&As[kk][ty*8 + 4];
            float4 bv = *(float4*)&Bs[kk][tx*4];
            u64 a2[4] = { a01.x, a01.y, a23.x, a23.y };
            u64 b2[4] = { dup2(bv.x), dup2(bv.y), dup2(bv.z), dup2(bv.w) };
#pragma unroll
            for (int i = 0; i < 4; i++)
#pragma unroll
                for (int j = 0; j < 4; j++)
                    acc[i][j] = ffma2(a2[i], b2[j], acc[i][j]);
        }
        __syncthreads();
    }

    const int n = n0 + tx*4;
    if (headsplit) {
        const int hh = n >> 6;          // head index
        const int nc = n & 63;          // col within head
#pragma unroll
        for (int i = 0; i < 4; i++) {
            float2 c0 = unpk2(acc[i][0]), c1 = unpk2(acc[i][1]);
            float2 c2 = unpk2(acc[i][2]), c3 = unpk2(acc[i][3]);
            int m = m0 + ty*8 + 2*i;
            int bb = m >> 10, s = m & 1023;
            *(float4*)&out[((size_t)(bb*Hc + hh) * Sc + s) * DHc + nc] =
                make_float4(c0.x, c1.x, c2.x, c3.x);
            int m2 = m + 1, bb2 = m2 >> 10, s2 = m2 & 1023;
            *(float4*)&out[((size_t)(bb2*Hc + hh) * Sc + s2) * DHc + nc] =
                make_float4(c0.y, c1.y, c2.y, c3.y);
        }
    } else {
#pragma unroll
        for (int i = 0; i < 4; i++) {
            float2 c0 = unpk2(acc[i][0]), c1 = unpk2(acc[i][1]);
            float2 c2 = unpk2(acc[i][2]), c3 = unpk2(acc[i][3]);
            int m = m0 + ty*8 + 2*i;
            *(float4*)&out[(size_t)m * 512 + n] = make_float4(c0.x, c1.x, c2.x, c3.x);
            *(float4*)&out[(size_t)(m+1) * 512 + n] = make_float4(c0.y, c1.y, c2.y, c3.y);
        }
    }
}

// Merged 3-way projection: z selects (A, W, dst).
__global__ __launch_bounds__(256, 3) void proj3(const float* __restrict__ A0,
                                                const float* __restrict__ A1,
                                                const float* __restrict__ A2,
                                                const float* __restrict__ W0,
                                                const float* __restrict__ W1,
                                                const float* __restrict__ W2,
                                                float* __restrict__ O0,
                                                float* __restrict__ O1,
                                                float* __restrict__ O2) {
    const int z = blockIdx.z;
    const float* A = (z == 0) ? A0 : (z == 1) ? A1 : A2;
    const float* W = (z == 0) ? W0 : (z == 1) ? W1 : W2;
    float*       O = (z == 0) ? O0 : (z == 1) ? O1 : O2;
    gemm_body(A, W, O, 1);
}

__global__ __launch_bounds__(256, 3) void gemm512(const float* __restrict__ A,
                                                  const float* __restrict__ W,
                                                  float* __restrict__ out) {
    gemm_body(A, W, out, 0);
}

// ============================================================
// Fused causal attention with skewed relative bias (f32x2 math).
// bias[j,t] = sum_d q[j,d] * R[h][d][S-1-j+t]   (t <= j)
// smem aliasing: kv = K (QK phase) then V (PV phase);
//                rp = R window (QK phase), ps inside rp (PV phase).
// (R7-proven version: no V register prefetch — it spilled at occ 3.)
// ============================================================
__global__ __launch_bounds__(256, 3) void attn_kernel(const float* __restrict__ Rel) {
    extern __shared__ float sm[];
    float* qs = sm;                 // [d][j]  64x68   (persistent)
    float* kv = qs + 64*68;         // QK: K as [d][t] ; PV: V as [t][d]
    float* rp = kv + 64*68;         // QK: R as [d][cc] 64x128 ; PV: ps as [t][j]

    const int tid = threadIdx.x;
    const int tx = tid & 15, ty = tid >> 4;
    const int bh = blockIdx.y;
    const int h  = bh & (Hc-1);
    const int j0 = ((int)gridDim.x - 1 - (int)blockIdx.x) << 6;   // heavy first

    const float* Qp    = g_Q + ((size_t)bh * Sc + j0) * DHc;
    const float* Kbase = g_K + (size_t)bh * Sc * DHc;
    const float* Vbase = g_V + (size_t)bh * Sc * DHc;
    const float* Rp    = Rel + (size_t)h * DHc * Sc;

    for (int f = tid; f < 1024; f += 256) {
        int j = f >> 4, d4 = (f & 15) << 2;
        float4 v = *(const float4*)(Qp + j*DHc + d4);
        qs[(d4+0)*68 + j] = v.x; qs[(d4+1)*68 + j] = v.y;
        qs[(d4+2)*68 + j] = v.z; qs[(d4+3)*68 + j] = v.w;
    }

    float mrow[4] = {-1e30f, -1e30f, -1e30f, -1e30f};
    float lrow[4] = {0.f, 0.f, 0.f, 0.f};
    u64 oacc2[4][2];
#pragma unroll
    for (int i = 0; i < 4; i++) { oacc2[i][0] = 0ull; oacc2[i][1] = 0ull; }

    const int base0 = 60 + 4*tx - 4*ty;   // in [0,120], mult of 4
    const int ntiles = (j0 >> 6) + 1;

    for (int it = 0; it < ntiles; it++) {
        const int t0 = it << 6;
        __syncthreads();   // (a)

        for (int f = tid; f < 1024; f += 256) {
            int t = f >> 4, d4 = (f & 15) << 2;
            float4 k4 = *(const float4*)(Kbase + (size_t)(t0 + t)*DHc + d4);
            kv[(d4+0)*68 + t] = k4.x; kv[(d4+1)*68 + t] = k4.y;
            kv[(d4+2)*68 + t] = k4.z; kv[(d4+3)*68 + t] = k4.w;
        }
        const int cmin = Sc - 64 - j0 + t0;   // >= 0, multiple of 4
        for (int f = tid; f < 64*32; f += 256) {
            int d = f >> 5, cc4 = (f & 31) << 2;
            int col = cmin + cc4;
            float4 rv4 = (col < Sc) ? *(const float4*)(Rp + (size_t)d*Sc + col)
                                    : make_float4(0.f, 0.f, 0.f, 0.f);
            *(float4*)(rp + d*128 + cc4) = rv4;
        }
        __syncthreads();   // (b)

        // s[j][t] = q.k + q.R[:, S-1-j+t]  -- f32x2, pairs along t
        u64 acc2[4][2];
#pragma unroll
        for (int i = 0; i < 4; i++) { acc2[i][0] = 0ull; acc2[i][1] = 0ull; }
#pragma unroll 8
        for (int d = 0; d < 64; d++) {
            float4 qv = *(float4*)(qs + d*68 + ty*4);
            ulonglong2 kk2 = *(ulonglong2*)(kv + d*68 + tx*4);
            float4 r0 = *(float4*)(rp + d*128 + base0);
            float4 r1 = *(float4*)(rp + d*128 + base0 + 4);
            u64 qa2[4] = { dup2(qv.x), dup2(qv.y), dup2(qv.z), dup2(qv.w) };
            u64 e0 = pack2(r0.x, r0.y), e1 = pack2(r0.z, r0.w), e2 = pack2(r1.x, r1.y);
            u64 o1 = pack2(r0.y, r0.z), o3 = pack2(r0.w, r1.x), o5 = pack2(r1.y, r1.z);
            u64 rb00 = o3, rb01 = o5;   // i=0
            u64 rb10 = e1, rb11 = e2;   // i=1
            u64 rb20 = o1, rb21 = o3;   // i=2
            u64 rb30 = e0, rb31 = e1;   // i=3
            acc2[0][0] = ffma2(qa2[0], kk2.x, acc2[0][0]);
            acc2[0][1] = ffma2(qa2[0], kk2.y, acc2[0][1]);
            acc2[0][0] = ffma2(qa2[0], rb00,  acc2[0][0]);
            acc2[0][1] = ffma2(qa2[0], rb01,  acc2[0][1]);
            acc2[1][0] = ffma2(qa2[1], kk2.x, acc2[1][0]);
            acc2[1][1] = ffma2(qa2[1], kk2.y, acc2[1][1]);
            acc2[1][0] = ffma2(qa2[1], rb10,  acc2[1][0]);
            acc2[1][1] = ffma2(qa2[1], rb11,  acc2[1][1]);
            acc2[2][0] = ffma2(qa2[2], kk2.x, acc2[2][0]);
            acc2[2][1] = ffma2(qa2[2], kk2.y, acc2[2][1]);
            acc2[2][0] = ffma2(qa2[2], rb20,  acc2[2][0]);
            acc2[2][1] = ffma2(qa2[2], rb21,  acc2[2][1]);
            acc2[3][0] = ffma2(qa2[3], kk2.x, acc2[3][0]);
            acc2[3][1] = ffma2(qa2[3], kk2.y, acc2[3][1]);
            acc2[3][0] = ffma2(qa2[3], rb30,  acc2[3][0]);
            acc2[3][1] = ffma2(qa2[3], rb31,  acc2[3][1]);
        }

        float acc[4][4];
#pragma unroll
        for (int i = 0; i < 4; i++) {
            float2 u0 = unpk2(acc2[i][0]), u1 = unpk2(acc2[i][1]);
            acc[i][0] = u0.x; acc[i][1] = u0.y; acc[i][2] = u1.x; acc[i][3] = u1.y;
        }

        // online softmax (scale AFTER bias+mask, matching reference)
#pragma unroll
        for (int i = 0; i < 4; i++) {
            const int j = j0 + ty*4 + i;
            float mx = -1e30f;
#pragma unroll
            for (int c = 0; c < 4; c++) {
                int t = t0 + tx*4 + c;
                float v = (t <= j) ? acc[i][c] * 0.125f : -1e30f;
                acc[i][c] = v;
                mx = fmaxf(mx, v);
            }
#pragma unroll
            for (int off = 8; off; off >>= 1)
                mx = fmaxf(mx, __shfl_xor_sync(0xffffffffu, mx, off, 16));
            float mnew = fmaxf(mrow[i], mx);
            float corr = __expf(mrow[i] - mnew);
            float ss = 0.f;
#pragma unroll
            for (int c = 0; c < 4; c++) {
                float p = __expf(acc[i][c] - mnew);
                acc[i][c] = p;
                ss += p;
            }
#pragma unroll
            for (int off = 8; off; off >>= 1)
                ss += __shfl_xor_sync(0xffffffffu, ss, off, 16);
            lrow[i] = lrow[i] * corr + ss;
            mrow[i] = mnew;
            u64 corr2 = dup2(corr);
            oacc2[i][0] = fmul2(oacc2[i][0], corr2);
            oacc2[i][1] = fmul2(oacc2[i][1], corr2);
        }
        __syncthreads();   // (c)

        // store p transposed: ps[t][j] (inside rp), load V -> kv[t][d]
        float* ps = rp;
#pragma unroll
        for (int c = 0; c < 4; c++) {
            float4 pv = make_float4(acc[0][c], acc[1][c], acc[2][c], acc[3][c]);
            *(float4*)(ps + (tx*4 + c)*68 + ty*4) = pv;
        }
        for (int f = tid; f < 1024; f += 256) {
            int t = f >> 4, d4 = (f & 15) << 2;
            float4 vv = *(const float4*)(Vbase + (size_t)(t0 + t)*DHc + d4);
            *(float4*)(kv + t*68 + d4) = vv;
        }
        __syncthreads();   // (d)

        // O += P @ V  (f32x2, pairs along DH cols)
#pragma unroll 8
        for (int t = 0; t < 64; t++) {
            ulonglong2 vv2 = *(ulonglong2*)(kv + t*68 + tx*4);
            float4 p4 = *(float4*)(ps + t*68 + ty*4);
            u64 pa0 = dup2(p4.x), pa1 = dup2(p4.y), pa2v = dup2(p4.z), pa3 = dup2(p4.w);
            oacc2[0][0] = ffma2(pa0,  vv2.x, oacc2[0][0]);
            oacc2[0][1] = ffma2(pa0,  vv2.y, oacc2[0][1]);
            oacc2[1][0] = ffma2(pa1,  vv2.x, oacc2[1][0]);
            oacc2[1][1] = ffma2(pa1,  vv2.y, oacc2[1][1]);
            oacc2[2][0] = ffma2(pa2v, vv2.x, oacc2[2][0]);
            oacc2[2][1] = ffma2(pa2v, vv2.y, oacc2[2][1]);
            oacc2[3][0] = ffma2(pa3,  vv2.x, oacc2[3][0]);
            oacc2[3][1] = ffma2(pa3,  vv2.y, oacc2[3][1]);
        }
    }

    // epilogue: ctx[b][j][h*64 + dc]
    const int b = bh >> 3;
#pragma unroll
    for (int i = 0; i < 4; i++) {
        float inv = 1.f / lrow[i];
        float2 u0 = unpk2(oacc2[i][0]), u1 = unpk2(oacc2[i][1]);
        float4 o = make_float4(u0.x*inv, u0.y*inv, u1.x*inv, u1.y*inv);
        *(float4*)&g_ctx[((size_t)(b*Sc + j0 + ty*4 + i)) * Dc + h*DHc + tx*4] = o;
    }
}

// ============================================================
extern "C" void kernel_launch(void* const* d_in, const int* in_sizes, int n_in,
                              void* d_out, int out_size) {
    (void)in_sizes; (void)n_in; (void)out_size;
    const float* queries = (const float*)d_in[0];
    const float* keysp   = (const float*)d_in[1];
    const float* valuesp = (const float*)d_in[2];
    // d_in[3] = mask (causal; applied analytically)
    const float* Wq  = (const float*)d_in[4];
    const float* Wk  = (const float*)d_in[5];
    const float* Wv  = (const float*)d_in[6];
    const float* Wo  = (const float*)d_in[7];
    const float* rel = (const float*)d_in[8];
    float* out = (float*)d_out;

    float *pQ, *pK, *pV, *pC;
    cudaGetSymbolAddress((void**)&pQ, g_Q);
    cudaGetSymbolAddress((void**)&pK, g_K);
    cudaGetSymbolAddress((void**)&pV, g_V);
    cudaGetSymbolAddress((void**)&pC, g_ctx);

    // fused QKV projections: 128x64 tiles, z selects projection
    proj3<<<dim3(Dc/64, (Bc*Sc)/128, 3), 256>>>(queries, keysp, valuesp,
                                                Wq, Wk, Wv, pQ, pK, pV);

    const int smem = (2*64*68 + 64*128) * (int)sizeof(float);   // 67584 B -> 3 CTAs/SM
    cudaFuncSetAttribute(attn_kernel, cudaFuncAttributeMaxDynamicSharedMemorySize, smem);
    attn_kernel<<<dim3(Sc/64, Bc*Hc), 256, smem>>>(rel);

    gemm512<<<dim3(Dc/64, (Bc*Sc)/128), 256>>>(pC, Wo, out);
}

// round 13
// speedup vs baseline: 1.6369x; 1.0669x over previous
#include <cuda_runtime.h>

#define Bc 4
#define Sc 1024
#define Dc 512
#define Hc 8
#define DHc 64
#define Mt (Bc*Sc)          // 4096 rows of activations

typedef unsigned long long u64;

// ---- f32x2 packed-math helpers (FFMA2 path: ptxas only emits via PTX) ----
__device__ __forceinline__ u64 ffma2(u64 a, u64 b, u64 c) {
    u64 d;
    asm("fma.rn.f32x2 %0, %1, %2, %3;" : "=l"(d) : "l"(a), "l"(b), "l"(c));
    return d;
}
__device__ __forceinline__ u64 fmul2(u64 a, u64 b) {
    u64 d;
    asm("mul.rn.f32x2 %0, %1, %2;" : "=l"(d) : "l"(a), "l"(b));
    return d;
}
__device__ __forceinline__ u64 pack2(float lo, float hi) {
    u64 d;
    asm("mov.b64 %0, {%1, %2};" : "=l"(d)
        : "r"(__float_as_uint(lo)), "r"(__float_as_uint(hi)));
    return d;
}
__device__ __forceinline__ u64 dup2(float x) { return pack2(x, x); }
__device__ __forceinline__ float2 unpk2(u64 v) {
    unsigned lo, hi;
    asm("mov.b64 {%0, %1}, %2;" : "=r"(lo), "=r"(hi) : "l"(v));
    return make_float2(__uint_as_float(lo), __uint_as_float(hi));
}

// ---- cp.async helpers ----
__device__ __forceinline__ void cpa16(unsigned dst, const void* src) {
    asm volatile("cp.async.ca.shared.global [%0], [%1], 16;" :: "r"(dst), "l"(src));
}
__device__ __forceinline__ void cpa_commit() {
    asm volatile("cp.async.commit_group;");
}
__device__ __forceinline__ void cpa_wait0() {
    asm volatile("cp.async.wait_group 0;" ::: "memory");
}

// ---- scratch (no allocations allowed) ----
__device__ float g_Q[Bc*Hc*Sc*DHc];    // [B,H,S,DH]
__device__ float g_K[Bc*Hc*Sc*DHc];
__device__ float g_V[Bc*Hc*Sc*DHc];
__device__ float g_ctx[Bc*Sc*Dc];      // [B,S,D]
__device__ float g_AT[3*Dc*Mt];        // transposed activations [3][512][4096]
__device__ float g_CT[Dc*Mt];          // transposed ctx [512][4096]

// ============================================================
// Tiled transpose: in[M=4096][N=512] -> out[N=512][M=4096]
// ============================================================
__device__ __forceinline__ void transpose_body(const float* __restrict__ in,
                                               float* __restrict__ out) {
    __shared__ float t[32][33];
    const int lx = threadIdx.x & 31, ly = threadIdx.x >> 5;   // 32 x 8
    const int bx = blockIdx.x << 5;   // col base in input (N dim)
    const int by = blockIdx.y << 5;   // row base in input (M dim)
#pragma unroll
    for (int u = 0; u < 4; u++)
        t[ly + u*8][lx] = in[(size_t)(by + ly + u*8) * Dc + bx + lx];
    __syncthreads();
#pragma unroll
    for (int u = 0; u < 4; u++)
        out[(size_t)(bx + ly + u*8) * Mt + by + lx] = t[lx][ly + u*8];
}

__global__ __launch_bounds__(256) void transpose3(const float* __restrict__ q,
                                                  const float* __restrict__ k,
                                                  const float* __restrict__ v) {
    const int z = blockIdx.z;
    const float* in = (z == 0) ? q : (z == 1) ? k : v;
    transpose_body(in, g_AT + (size_t)z * Dc * Mt);
}

__global__ __launch_bounds__(256) void transpose1() {
    transpose_body(g_ctx, g_CT);
}

// ============================================================
// GEMM (cp.async pipelined): out = A[M,512] @ W[512,512],
// A supplied TRANSPOSED as AT[512][4096].
// 128x64 block tile, 256 threads, 8(m)x4(n) f32x2 micro-tile.
// Double-buffered smem, loads via LDGSTS (no register staging),
// ONE __syncthreads per k-step.
// ============================================================
__device__ __forceinline__ void gemm_ca(const float* __restrict__ AT,
                                        const float* __restrict__ W,
                                        float* __restrict__ out,
                                        int headsplit) {
    __shared__ float As[2][16][132];   // [buf][k][m]  (528B rows, 16B-aligned)
    __shared__ float Bs[2][16][68];    // [buf][k][n]  (272B rows, 16B-aligned)
    const int tid = threadIdx.x;
    const int tx = tid & 15;        // n-group
    const int ty = tid >> 4;        // m-group
    const int m0 = blockIdx.y << 7, n0 = blockIdx.x << 6;

    // A tile: 16 rows x 512B = 512 x 16B chunks -> 2 per thread
    const int arow0 = tid >> 5;           // chunk set 0: rows 0..7
    const int acol0 = (tid & 31) << 2;    // float col (x4)
    // B tile: 16 rows x 256B = 256 chunks -> 1 per thread
    const int brow = tid >> 4;
    const int bcol = (tid & 15) << 2;

    const unsigned aB0 = (unsigned)__cvta_generic_to_shared(&As[0][0][0]);
    const unsigned aB1 = (unsigned)__cvta_generic_to_shared(&As[1][0][0]);
    const unsigned bB0 = (unsigned)__cvta_generic_to_shared(&Bs[0][0][0]);
    const unsigned bB1 = (unsigned)__cvta_generic_to_shared(&Bs[1][0][0]);

    const float* Abase = AT + m0 + (size_t)arow0 * Mt + acol0;
    const float* Wbase = W + n0 + (size_t)brow * Dc + bcol;

    u64 acc[4][4];
#pragma unroll
    for (int i = 0; i < 4; i++)
#pragma unroll
        for (int j = 0; j < 4; j++) acc[i][j] = 0ull;

    // --- issue helper (macro-free inline) ---
    auto issue = [&](int buf, int k0) {
        const unsigned aB = buf ? aB1 : aB0;
        const unsigned bB = buf ? bB1 : bB0;
        // A: rows arow0 and arow0+8
        cpa16(aB + (unsigned)(arow0 * 132 + acol0) * 4,
              Abase + (size_t)k0 * Mt);
        cpa16(aB + (unsigned)((arow0 + 8) * 132 + acol0) * 4,
              Abase + (size_t)(k0 + 8) * Mt);
        // B
        cpa16(bB + (unsigned)(brow * 68 + bcol) * 4,
              Wbase + (size_t)k0 * Dc);
    };

    issue(0, 0);
    cpa_commit();

    int buf = 0;
#pragma unroll 1
    for (int k0 = 0; k0 < 512; k0 += 16) {
        cpa_wait0();
        __syncthreads();            // all threads' chunks for buf visible
        if (k0 + 16 < 512) {        // prefetch next tile into other buffer
            issue(buf ^ 1, k0 + 16);
            cpa_commit();
        }
#pragma unroll
        for (int kk = 0; kk < 16; kk++) {
            ulonglong2 a01 = *(ulonglong2*)&As[buf][kk][ty*8];
            ulonglong2 a23 = *(ulonglong2*)&As[buf][kk][ty*8 + 4];
            float4 bv = *(float4*)&Bs[buf][kk][tx*4];
            u64 a2[4] = { a01.x, a01.y, a23.x, a23.y };
            u64 b2[4] = { dup2(bv.x), dup2(bv.y), dup2(bv.z), dup2(bv.w) };
#pragma unroll
            for (int i = 0; i < 4; i++)
#pragma unroll
                for (int j = 0; j < 4; j++)
                    acc[i][j] = ffma2(a2[i], b2[j], acc[i][j]);
        }
        buf ^= 1;
    }

    const int n = n0 + tx*4;
    if (headsplit) {
        const int hh = n >> 6;          // head index
        const int nc = n & 63;          // col within head
#pragma unroll
        for (int i = 0; i < 4; i++) {
            float2 c0 = unpk2(acc[i][0]), c1 = unpk2(acc[i][1]);
            float2 c2 = unpk2(acc[i][2]), c3 = unpk2(acc[i][3]);
            int m = m0 + ty*8 + 2*i;
            int bb = m >> 10, s = m & 1023;
            *(float4*)&out[((size_t)(bb*Hc + hh) * Sc + s) * DHc + nc] =
                make_float4(c0.x, c1.x, c2.x, c3.x);
            int m2 = m + 1, bb2 = m2 >> 10, s2 = m2 & 1023;
            *(float4*)&out[((size_t)(bb2*Hc + hh) * Sc + s2) * DHc + nc] =
                make_float4(c0.y, c1.y, c2.y, c3.y);
        }
    } else {
#pragma unroll
        for (int i = 0; i < 4; i++) {
            float2 c0 = unpk2(acc[i][0]), c1 = unpk2(acc[i][1]);
            float2 c2 = unpk2(acc[i][2]), c3 = unpk2(acc[i][3]);
            int m = m0 + ty*8 + 2*i;
            *(float4*)&out[(size_t)m * 512 + n] = make_float4(c0.x, c1.x, c2.x, c3.x);
            *(float4*)&out[(size_t)(m+1) * 512 + n] = make_float4(c0.y, c1.y, c2.y, c3.y);
        }
    }
}

// Merged 3-way projection: z selects (AT slice, W, dst).
__global__ __launch_bounds__(256, 3) void proj3(const float* __restrict__ W0,
                                                const float* __restrict__ W1,
                                                const float* __restrict__ W2,
                                                float* __restrict__ O0,
                                                float* __restrict__ O1,
                                                float* __restrict__ O2) {
    const int z = blockIdx.z;
    const float* AT = g_AT + (size_t)z * Dc * Mt;
    const float* W = (z == 0) ? W0 : (z == 1) ? W1 : W2;
    float*       O = (z == 0) ? O0 : (z == 1) ? O1 : O2;
    gemm_ca(AT, W, O, 1);
}

__global__ __launch_bounds__(256, 3) void gemm_out(const float* __restrict__ W,
                                                   float* __restrict__ out) {
    gemm_ca(g_CT, W, out, 0);
}

// ============================================================
// Fused causal attention with skewed relative bias (f32x2 math).
// bias[j,t] = sum_d q[j,d] * R[h][d][S-1-j+t]   (t <= j)
// smem aliasing: kv = K (QK phase) then V (PV phase);
//                rp = R window (QK phase), ps inside rp (PV phase).
// (R7/R12-proven version.)
// ============================================================
__global__ __launch_bounds__(256, 3) void attn_kernel(const float* __restrict__ Rel) {
    extern __shared__ float sm[];
    float* qs = sm;                 // [d][j]  64x68   (persistent)
    float* kv = qs + 64*68;         // QK: K as [d][t] ; PV: V as [t][d]
    float* rp = kv + 64*68;         // QK: R as [d][cc] 64x128 ; PV: ps as [t][j]

    const int tid = threadIdx.x;
    const int tx = tid & 15, ty = tid >> 4;
    const int bh = blockIdx.y;
    const int h  = bh & (Hc-1);
    const int j0 = ((int)gridDim.x - 1 - (int)blockIdx.x) << 6;   // heavy first

    const float* Qp    = g_Q + ((size_t)bh * Sc + j0) * DHc;
    const float* Kbase = g_K + (size_t)bh * Sc * DHc;
    const float* Vbase = g_V + (size_t)bh * Sc * DHc;
    const float* Rp    = Rel + (size_t)h * DHc * Sc;

    for (int f = tid; f < 1024; f += 256) {
        int j = f >> 4, d4 = (f & 15) << 2;
        float4 v = *(const float4*)(Qp + j*DHc + d4);
        qs[(d4+0)*68 + j] = v.x; qs[(d4+1)*68 + j] = v.y;
        qs[(d4+2)*68 + j] = v.z; qs[(d4+3)*68 + j] = v.w;
    }

    float mrow[4] = {-1e30f, -1e30f, -1e30f, -1e30f};
    float lrow[4] = {0.f, 0.f, 0.f, 0.f};
    u64 oacc2[4][2];
#pragma unroll
    for (int i = 0; i < 4; i++) { oacc2[i][0] = 0ull; oacc2[i][1] = 0ull; }

    const int base0 = 60 + 4*tx - 4*ty;   // in [0,120], mult of 4
    const int ntiles = (j0 >> 6) + 1;

    for (int it = 0; it < ntiles; it++) {
        const int t0 = it << 6;
        __syncthreads();   // (a)

        for (int f = tid; f < 1024; f += 256) {
            int t = f >> 4, d4 = (f & 15) << 2;
            float4 k4 = *(const float4*)(Kbase + (size_t)(t0 + t)*DHc + d4);
            kv[(d4+0)*68 + t] = k4.x; kv[(d4+1)*68 + t] = k4.y;
            kv[(d4+2)*68 + t] = k4.z; kv[(d4+3)*68 + t] = k4.w;
        }
        const int cmin = Sc - 64 - j0 + t0;   // >= 0, multiple of 4
        for (int f = tid; f < 64*32; f += 256) {
            int d = f >> 5, cc4 = (f & 31) << 2;
            int col = cmin + cc4;
            float4 rv4 = (col < Sc) ? *(const float4*)(Rp + (size_t)d*Sc + col)
                                    : make_float4(0.f, 0.f, 0.f, 0.f);
            *(float4*)(rp + d*128 + cc4) = rv4;
        }
        __syncthreads();   // (b)

        // s[j][t] = q.k + q.R[:, S-1-j+t]  -- f32x2, pairs along t
        u64 acc2[4][2];
#pragma unroll
        for (int i = 0; i < 4; i++) { acc2[i][0] = 0ull; acc2[i][1] = 0ull; }
#pragma unroll 8
        for (int d = 0; d < 64; d++) {
            float4 qv = *(float4*)(qs + d*68 + ty*4);
            ulonglong2 kk2 = *(ulonglong2*)(kv + d*68 + tx*4);
            float4 r0 = *(float4*)(rp + d*128 + base0);
            float4 r1 = *(float4*)(rp + d*128 + base0 + 4);
            u64 qa2[4] = { dup2(qv.x), dup2(qv.y), dup2(qv.z), dup2(qv.w) };
            u64 e0 = pack2(r0.x, r0.y), e1 = pack2(r0.z, r0.w), e2 = pack2(r1.x, r1.y);
            u64 o1 = pack2(r0.y, r0.z), o3 = pack2(r0.w, r1.x), o5 = pack2(r1.y, r1.z);
            u64 rb00 = o3, rb01 = o5;   // i=0
            u64 rb10 = e1, rb11 = e2;   // i=1
            u64 rb20 = o1, rb21 = o3;   // i=2
            u64 rb30 = e0, rb31 = e1;   // i=3
            acc2[0][0] = ffma2(qa2[0], kk2.x, acc2[0][0]);
            acc2[0][1] = ffma2(qa2[0], kk2.y, acc2[0][1]);
            acc2[0][0] = ffma2(qa2[0], rb00,  acc2[0][0]);
            acc2[0][1] = ffma2(qa2[0], rb01,  acc2[0][1]);
            acc2[1][0] = ffma2(qa2[1], kk2.x, acc2[1][0]);
            acc2[1][1] = ffma2(qa2[1], kk2.y, acc2[1][1]);
            acc2[1][0] = ffma2(qa2[1], rb10,  acc2[1][0]);
            acc2[1][1] = ffma2(qa2[1], rb11,  acc2[1][1]);
            acc2[2][0] = ffma2(qa2[2], kk2.x, acc2[2][0]);
            acc2[2][1] = ffma2(qa2[2], kk2.y, acc2[2][1]);
            acc2[2][0] = ffma2(qa2[2], rb20,  acc2[2][0]);
            acc2[2][1] = ffma2(qa2[2], rb21,  acc2[2][1]);
            acc2[3][0] = ffma2(qa2[3], kk2.x, acc2[3][0]);
            acc2[3][1] = ffma2(qa2[3], kk2.y, acc2[3][1]);
            acc2[3][0] = ffma2(qa2[3], rb30,  acc2[3][0]);
            acc2[3][1] = ffma2(qa2[3], rb31,  acc2[3][1]);
        }

        float acc[4][4];
#pragma unroll
        for (int i = 0; i < 4; i++) {
            float2 u0 = unpk2(acc2[i][0]), u1 = unpk2(acc2[i][1]);
            acc[i][0] = u0.x; acc[i][1] = u0.y; acc[i][2] = u1.x; acc[i][3] = u1.y;
        }

        // online softmax (scale AFTER bias+mask, matching reference)
#pragma unroll
        for (int i = 0; i < 4; i++) {
            const int j = j0 + ty*4 + i;
            float mx = -1e30f;
#pragma unroll
            for (int c = 0; c < 4; c++) {
                int t = t0 + tx*4 + c;
                float v = (t <= j) ? acc[i][c] * 0.125f : -1e30f;
                acc[i][c] = v;
                mx = fmaxf(mx, v);
            }
#pragma unroll
            for (int off = 8; off; off >>= 1)
                mx = fmaxf(mx, __shfl_xor_sync(0xffffffffu, mx, off, 16));
            float mnew = fmaxf(mrow[i], mx);
            float corr = __expf(mrow[i] - mnew);
            float ss = 0.f;
#pragma unroll
            for (int c = 0; c < 4; c++) {
                float p = __expf(acc[i][c] - mnew);
                acc[i][c] = p;
                ss += p;
            }
#pragma unroll
            for (int off = 8; off; off >>= 1)
                ss += __shfl_xor_sync(0xffffffffu, ss, off, 16);
            lrow[i] = lrow[i] * corr + ss;
            mrow[i] = mnew;
            u64 corr2 = dup2(corr);
            oacc2[i][0] = fmul2(oacc2[i][0], corr2);
            oacc2[i][1] = fmul2(oacc2[i][1], corr2);
        }
        __syncthreads();   // (c)

        // store p transposed: ps[t][j] (inside rp), load V -> kv[t][d]
        float* ps = rp;
#pragma unroll
        for (int c = 0; c < 4; c++) {
            float4 pv = make_float4(acc[0][c], acc[1][c], acc[2][c], acc[3][c]);
            *(float4*)(ps + (tx*4 + c)*68 + ty*4) = pv;
        }
        for (int f = tid; f < 1024; f += 256) {
            int t = f >> 4, d4 = (f & 15) << 2;
            float4 vv = *(const float4*)(Vbase + (size_t)(t0 + t)*DHc + d4);
            *(float4*)(kv + t*68 + d4) = vv;
        }
        __syncthreads();   // (d)

        // O += P @ V  (f32x2, pairs along DH cols)
#pragma unroll 8
        for (int t = 0; t < 64; t++) {
            ulonglong2 vv2 = *(ulonglong2*)(kv + t*68 + tx*4);
            float4 p4 = *(float4*)(ps + t*68 + ty*4);
            u64 pa0 = dup2(p4.x), pa1 = dup2(p4.y), pa2v = dup2(p4.z), pa3 = dup2(p4.w);
            oacc2[0][0] = ffma2(pa0,  vv2.x, oacc2[0][0]);
            oacc2[0][1] = ffma2(pa0,  vv2.y, oacc2[0][1]);
            oacc2[1][0] = ffma2(pa1,  vv2.x, oacc2[1][0]);
            oacc2[1][1] = ffma2(pa1,  vv2.y, oacc2[1][1]);
            oacc2[2][0] = ffma2(pa2v, vv2.x, oacc2[2][0]);
            oacc2[2][1] = ffma2(pa2v, vv2.y, oacc2[2][1]);
            oacc2[3][0] = ffma2(pa3,  vv2.x, oacc2[3][0]);
            oacc2[3][1] = ffma2(pa3,  vv2.y, oacc2[3][1]);
        }
    }

    // epilogue: ctx[b][j][h*64 + dc]
    const int b = bh >> 3;
#pragma unroll
    for (int i = 0; i < 4; i++) {
        float inv = 1.f / lrow[i];
        float2 u0 = unpk2(oacc2[i][0]), u1 = unpk2(oacc2[i][1]);
        float4 o = make_float4(u0.x*inv, u0.y*inv, u1.x*inv, u1.y*inv);
        *(float4*)&g_ctx[((size_t)(b*Sc + j0 + ty*4 + i)) * Dc + h*DHc + tx*4] = o;
    }
}

// ============================================================
extern "C" void kernel_launch(void* const* d_in, const int* in_sizes, int n_in,
                              void* d_out, int out_size) {
    (void)in_sizes; (void)n_in; (void)out_size;
    const float* queries = (const float*)d_in[0];
    const float* keysp   = (const float*)d_in[1];
    const float* valuesp = (const float*)d_in[2];
    // d_in[3] = mask (causal; applied analytically)
    const float* Wq  = (const float*)d_in[4];
    const float* Wk  = (const float*)d_in[5];
    const float* Wv  = (const float*)d_in[6];
    const float* Wo  = (const float*)d_in[7];
    const float* rel = (const float*)d_in[8];
    float* out = (float*)d_out;

    float *pQ, *pK, *pV;
    cudaGetSymbolAddress((void**)&pQ, g_Q);
    cudaGetSymbolAddress((void**)&pK, g_K);
    cudaGetSymbolAddress((void**)&pV, g_V);

    // 1) transpose activations -> g_AT  [3][512][4096]
    transpose3<<<dim3(Dc/32, Mt/32, 3), 256>>>(queries, keysp, valuesp);

    // 2) fused QKV projections (cp.async pipelined GEMM)
    proj3<<<dim3(Dc/64, Mt/128, 3), 256>>>(Wq, Wk, Wv, pQ, pK, pV);

    // 3) attention
    const int smem = (2*64*68 + 64*128) * (int)sizeof(float);   // 67584 B -> 3 CTAs/SM
    cudaFuncSetAttribute(attn_kernel, cudaFuncAttributeMaxDynamicSharedMemorySize, smem);
    attn_kernel<<<dim3(Sc/64, Bc*Hc), 256, smem>>>(rel);

    // 4) transpose ctx -> g_CT, then output projection
    transpose1<<<dim3(Dc/32, Mt/32), 256>>>();
    gemm_out<<<dim3(Dc/64, Mt/128), 256>>>(Wo, out);
}

// round 14
// speedup vs baseline: 1.7165x; 1.0486x over previous
#include <cuda_runtime.h>

#define Bc 4
#define Sc 1024
#define Dc 512
#define Hc 8
#define DHc 64
#define Mt (Bc*Sc)          // 4096 rows of activations

typedef unsigned long long u64;

// ---- f32x2 packed-math helpers (FFMA2 path: ptxas only emits via PTX) ----
__device__ __forceinline__ u64 ffma2(u64 a, u64 b, u64 c) {
    u64 d;
    asm("fma.rn.f32x2 %0, %1, %2, %3;" : "=l"(d) : "l"(a), "l"(b), "l"(c));
    return d;
}
__device__ __forceinline__ u64 fmul2(u64 a, u64 b) {
    u64 d;
    asm("mul.rn.f32x2 %0, %1, %2;" : "=l"(d) : "l"(a), "l"(b));
    return d;
}
__device__ __forceinline__ u64 pack2(float lo, float hi) {
    u64 d;
    asm("mov.b64 %0, {%1, %2};" : "=l"(d)
        : "r"(__float_as_uint(lo)), "r"(__float_as_uint(hi)));
    return d;
}
__device__ __forceinline__ u64 dup2(float x) { return pack2(x, x); }
__device__ __forceinline__ float2 unpk2(u64 v) {
    unsigned lo, hi;
    asm("mov.b64 {%0, %1}, %2;" : "=r"(lo), "=r"(hi) : "l"(v));
    return make_float2(__uint_as_float(lo), __uint_as_float(hi));
}

// ---- cp.async helpers ----
__device__ __forceinline__ void cpa16(unsigned dst, const void* src) {
    asm volatile("cp.async.ca.shared.global [%0], [%1], 16;" :: "r"(dst), "l"(src));
}
__device__ __forceinline__ void cpa_commit() {
    asm volatile("cp.async.commit_group;");
}
__device__ __forceinline__ void cpa_wait0() {
    asm volatile("cp.async.wait_group 0;" ::: "memory");
}

// ---- scratch (no allocations allowed) ----
__device__ float g_Q[Bc*Hc*Sc*DHc];    // [B,H,S,DH]
__device__ float g_K[Bc*Hc*Sc*DHc];
__device__ float g_V[Bc*Hc*Sc*DHc];
__device__ float g_ctx[Bc*Sc*Dc];      // [B,S,D]
__device__ float g_AT[3*Dc*Mt];        // transposed activations [3][512][4096]
__device__ float g_CT[Dc*Mt];          // transposed ctx [512][4096]
// split-K attention partials: [32 bh][8 split j-tiles][2 chunks][64 rows][68]
// row layout: 64 O-cols, then m at [64], l at [65]
__device__ float g_part[32*8*2*64*68];

// ============================================================
// Tiled transpose: in[M=4096][N=512] -> out[N=512][M=4096]
// ============================================================
__device__ __forceinline__ void transpose_body(const float* __restrict__ in,
                                               float* __restrict__ out) {
    __shared__ float t[32][33];
    const int lx = threadIdx.x & 31, ly = threadIdx.x >> 5;   // 32 x 8
    const int bx = blockIdx.x << 5;   // col base in input (N dim)
    const int by = blockIdx.y << 5;   // row base in input (M dim)
#pragma unroll
    for (int u = 0; u < 4; u++)
        t[ly + u*8][lx] = in[(size_t)(by + ly + u*8) * Dc + bx + lx];
    __syncthreads();
#pragma unroll
    for (int u = 0; u < 4; u++)
        out[(size_t)(bx + ly + u*8) * Mt + by + lx] = t[lx][ly + u*8];
}

__global__ __launch_bounds__(256) void transpose3(const float* __restrict__ q,
                                                  const float* __restrict__ k,
                                                  const float* __restrict__ v) {
    const int z = blockIdx.z;
    const float* in = (z == 0) ? q : (z == 1) ? k : v;
    transpose_body(in, g_AT + (size_t)z * Dc * Mt);
}

__global__ __launch_bounds__(256) void transpose1() {
    transpose_body(g_ctx, g_CT);
}

// ============================================================
// GEMM (cp.async pipelined): out = A[M,512] @ W[512,512],
// A supplied TRANSPOSED as AT[512][4096].
// 128x64 block tile, 256 threads, 8(m)x4(n) f32x2 micro-tile.
// ============================================================
__device__ __forceinline__ void gemm_ca(const float* __restrict__ AT,
                                        const float* __restrict__ W,
                                        float* __restrict__ out,
                                        int headsplit) {
    __shared__ float As[2][16][132];
    __shared__ float Bs[2][16][68];
    const int tid = threadIdx.x;
    const int tx = tid & 15;
    const int ty = tid >> 4;
    const int m0 = blockIdx.y << 7, n0 = blockIdx.x << 6;

    const int arow0 = tid >> 5;
    const int acol0 = (tid & 31) << 2;
    const int brow = tid >> 4;
    const int bcol = (tid & 15) << 2;

    const unsigned aB0 = (unsigned)__cvta_generic_to_shared(&As[0][0][0]);
    const unsigned aB1 = (unsigned)__cvta_generic_to_shared(&As[1][0][0]);
    const unsigned bB0 = (unsigned)__cvta_generic_to_shared(&Bs[0][0][0]);
    const unsigned bB1 = (unsigned)__cvta_generic_to_shared(&Bs[1][0][0]);

    const float* Abase = AT + m0 + (size_t)arow0 * Mt + acol0;
    const float* Wbase = W + n0 + (size_t)brow * Dc + bcol;

    u64 acc[4][4];
#pragma unroll
    for (int i = 0; i < 4; i++)
#pragma unroll
        for (int j = 0; j < 4; j++) acc[i][j] = 0ull;

    auto issue = [&](int buf, int k0) {
        const unsigned aB = buf ? aB1 : aB0;
        const unsigned bB = buf ? bB1 : bB0;
        cpa16(aB + (unsigned)(arow0 * 132 + acol0) * 4,
              Abase + (size_t)k0 * Mt);
        cpa16(aB + (unsigned)((arow0 + 8) * 132 + acol0) * 4,
              Abase + (size_t)(k0 + 8) * Mt);
        cpa16(bB + (unsigned)(brow * 68 + bcol) * 4,
              Wbase + (size_t)k0 * Dc);
    };

    issue(0, 0);
    cpa_commit();

    int buf = 0;
#pragma unroll 1
    for (int k0 = 0; k0 < 512; k0 += 16) {
        cpa_wait0();
        __syncthreads();
        if (k0 + 16 < 512) {
            issue(buf ^ 1, k0 + 16);
            cpa_commit();
        }
#pragma unroll
        for (int kk = 0; kk < 16; kk++) {
            ulonglong2 a01 = *(ulonglong2*)&As[buf][kk][ty*8];
            ulonglong2 a23 = *(ulonglong2*)&As[buf][kk][ty*8 + 4];
            float4 bv = *(float4*)&Bs[buf][kk][tx*4];
            u64 a2[4] = { a01.x, a01.y, a23.x, a23.y };
            u64 b2[4] = { dup2(bv.x), dup2(bv.y), dup2(bv.z), dup2(bv.w) };
#pragma unroll
            for (int i = 0; i < 4; i++)
#pragma unroll
                for (int j = 0; j < 4; j++)
                    acc[i][j] = ffma2(a2[i], b2[j], acc[i][j]);
        }
        buf ^= 1;
    }

    const int n = n0 + tx*4;
    if (headsplit) {
        const int hh = n >> 6;
        const int nc = n & 63;
#pragma unroll
        for (int i = 0; i < 4; i++) {
            float2 c0 = unpk2(acc[i][0]), c1 = unpk2(acc[i][1]);
            float2 c2 = unpk2(acc[i][2]), c3 = unpk2(acc[i][3]);
            int m = m0 + ty*8 + 2*i;
            int bb = m >> 10, s = m & 1023;
            *(float4*)&out[((size_t)(bb*Hc + hh) * Sc + s) * DHc + nc] =
                make_float4(c0.x, c1.x, c2.x, c3.x);
            int m2 = m + 1, bb2 = m2 >> 10, s2 = m2 & 1023;
            *(float4*)&out[((size_t)(bb2*Hc + hh) * Sc + s2) * DHc + nc] =
                make_float4(c0.y, c1.y, c2.y, c3.y);
        }
    } else {
#pragma unroll
        for (int i = 0; i < 4; i++) {
            float2 c0 = unpk2(acc[i][0]), c1 = unpk2(acc[i][1]);
            float2 c2 = unpk2(acc[i][2]), c3 = unpk2(acc[i][3]);
            int m = m0 + ty*8 + 2*i;
            *(float4*)&out[(size_t)m * 512 + n] = make_float4(c0.x, c1.x, c2.x, c3.x);
            *(float4*)&out[(size_t)(m+1) * 512 + n] = make_float4(c0.y, c1.y, c2.y, c3.y);
        }
    }
}

__global__ __launch_bounds__(256, 3) void proj3(const float* __restrict__ W0,
                                                const float* __restrict__ W1,
                                                const float* __restrict__ W2,
                                                float* __restrict__ O0,
                                                float* __restrict__ O1,
                                                float* __restrict__ O2) {
    const int z = blockIdx.z;
    const float* AT = g_AT + (size_t)z * Dc * Mt;
    const float* W = (z == 0) ? W0 : (z == 1) ? W1 : W2;
    float*       O = (z == 0) ? O0 : (z == 1) ? O1 : O2;
    gemm_ca(AT, W, O, 1);
}

__global__ __launch_bounds__(256, 3) void gemm_out(const float* __restrict__ W,
                                                   float* __restrict__ out) {
    gemm_ca(g_CT, W, out, 0);
}

// ============================================================
// Fused causal attention with skewed relative bias (f32x2 math),
// SPLIT-K over keys: j-tiles with >=9 kv-tiles are processed by
// 2 chunk-CTAs writing unnormalized partials (O, m, l); a combine
// kernel merges them. Chunk list ordered longest-first.
//   grid.x mapping (24 chunks per bh):
//     x in [0,16):  split j-tile jt = 15 - (x>>1), chunk ci = x&1
//     x in [16,24): single j-tile jt = 23 - x
// ============================================================
__global__ __launch_bounds__(256, 3) void attn_kernel(const float* __restrict__ Rel) {
    extern __shared__ float sm[];
    float* qs = sm;                 // [d][j]  64x68   (persistent)
    float* kv = qs + 64*68;         // QK: K as [d][t] ; PV: V as [t][d]
    float* rp = kv + 64*68;         // QK: R as [d][cc] 64x128 ; PV: ps as [t][j]

    const int tid = threadIdx.x;
    const int tx = tid & 15, ty = tid >> 4;
    const int bh = blockIdx.y;
    const int h  = bh & (Hc-1);

    // chunk decode
    const int x = blockIdx.x;
    int jt, tbeg, tend, ci = 0;
    bool split;
    if (x < 16) {
        jt = 15 - (x >> 1);
        ci = x & 1;
        const int nt = jt + 1;
        const int half = (nt + 1) >> 1;
        split = true;
        if (ci == 0) { tbeg = 0; tend = half; }
        else         { tbeg = half; tend = nt; }
    } else {
        jt = 23 - x;
        tbeg = 0; tend = jt + 1;
        split = false;
    }
    const int j0 = jt << 6;

    const float* Qp    = g_Q + ((size_t)bh * Sc + j0) * DHc;
    const float* Kbase = g_K + (size_t)bh * Sc * DHc;
    const float* Vbase = g_V + (size_t)bh * Sc * DHc;
    const float* Rp    = Rel + (size_t)h * DHc * Sc;

    for (int f = tid; f < 1024; f += 256) {
        int j = f >> 4, d4 = (f & 15) << 2;
        float4 v = *(const float4*)(Qp + j*DHc + d4);
        qs[(d4+0)*68 + j] = v.x; qs[(d4+1)*68 + j] = v.y;
        qs[(d4+2)*68 + j] = v.z; qs[(d4+3)*68 + j] = v.w;
    }

    float mrow[4] = {-1e30f, -1e30f, -1e30f, -1e30f};
    float lrow[4] = {0.f, 0.f, 0.f, 0.f};
    u64 oacc2[4][2];
#pragma unroll
    for (int i = 0; i < 4; i++) { oacc2[i][0] = 0ull; oacc2[i][1] = 0ull; }

    const int base0 = 60 + 4*tx - 4*ty;   // in [0,120], mult of 4

    for (int it = tbeg; it < tend; it++) {
        const int t0 = it << 6;
        __syncthreads();   // (a)

        for (int f = tid; f < 1024; f += 256) {
            int t = f >> 4, d4 = (f & 15) << 2;
            float4 k4 = *(const float4*)(Kbase + (size_t)(t0 + t)*DHc + d4);
            kv[(d4+0)*68 + t] = k4.x; kv[(d4+1)*68 + t] = k4.y;
            kv[(d4+2)*68 + t] = k4.z; kv[(d4+3)*68 + t] = k4.w;
        }
        const int cmin = Sc - 64 - j0 + t0;   // >= 0, multiple of 4
        for (int f = tid; f < 64*32; f += 256) {
            int d = f >> 5, cc4 = (f & 31) << 2;
            int col = cmin + cc4;
            float4 rv4 = (col < Sc) ? *(const float4*)(Rp + (size_t)d*Sc + col)
                                    : make_float4(0.f, 0.f, 0.f, 0.f);
            *(float4*)(rp + d*128 + cc4) = rv4;
        }
        __syncthreads();   // (b)

        // s[j][t] = q.k + q.R[:, S-1-j+t]  -- f32x2, pairs along t
        u64 acc2[4][2];
#pragma unroll
        for (int i = 0; i < 4; i++) { acc2[i][0] = 0ull; acc2[i][1] = 0ull; }
#pragma unroll 8
        for (int d = 0; d < 64; d++) {
            float4 qv = *(float4*)(qs + d*68 + ty*4);
            ulonglong2 kk2 = *(ulonglong2*)(kv + d*68 + tx*4);
            float4 r0 = *(float4*)(rp + d*128 + base0);
            float4 r1 = *(float4*)(rp + d*128 + base0 + 4);
            u64 qa2[4] = { dup2(qv.x), dup2(qv.y), dup2(qv.z), dup2(qv.w) };
            u64 e0 = pack2(r0.x, r0.y), e1 = pack2(r0.z, r0.w), e2 = pack2(r1.x, r1.y);
            u64 o1 = pack2(r0.y, r0.z), o3 = pack2(r0.w, r1.x), o5 = pack2(r1.y, r1.z);
            u64 rb00 = o3, rb01 = o5;   // i=0
            u64 rb10 = e1, rb11 = e2;   // i=1
            u64 rb20 = o1, rb21 = o3;   // i=2
            u64 rb30 = e0, rb31 = e1;   // i=3
            acc2[0][0] = ffma2(qa2[0], kk2.x, acc2[0][0]);
            acc2[0][1] = ffma2(qa2[0], kk2.y, acc2[0][1]);
            acc2[0][0] = ffma2(qa2[0], rb00,  acc2[0][0]);
            acc2[0][1] = ffma2(qa2[0], rb01,  acc2[0][1]);
            acc2[1][0] = ffma2(qa2[1], kk2.x, acc2[1][0]);
            acc2[1][1] = ffma2(qa2[1], kk2.y, acc2[1][1]);
            acc2[1][0] = ffma2(qa2[1], rb10,  acc2[1][0]);
            acc2[1][1] = ffma2(qa2[1], rb11,  acc2[1][1]);
            acc2[2][0] = ffma2(qa2[2], kk2.x, acc2[2][0]);
            acc2[2][1] = ffma2(qa2[2], kk2.y, acc2[2][1]);
            acc2[2][0] = ffma2(qa2[2], rb20,  acc2[2][0]);
            acc2[2][1] = ffma2(qa2[2], rb21,  acc2[2][1]);
            acc2[3][0] = ffma2(qa2[3], kk2.x, acc2[3][0]);
            acc2[3][1] = ffma2(qa2[3], kk2.y, acc2[3][1]);
            acc2[3][0] = ffma2(qa2[3], rb30,  acc2[3][0]);
            acc2[3][1] = ffma2(qa2[3], rb31,  acc2[3][1]);
        }

        float acc[4][4];
#pragma unroll
        for (int i = 0; i < 4; i++) {
            float2 u0 = unpk2(acc2[i][0]), u1 = unpk2(acc2[i][1]);
            acc[i][0] = u0.x; acc[i][1] = u0.y; acc[i][2] = u1.x; acc[i][3] = u1.y;
        }

        // online softmax (scale AFTER bias+mask, matching reference)
#pragma unroll
        for (int i = 0; i < 4; i++) {
            const int j = j0 + ty*4 + i;
            float mx = -1e30f;
#pragma unroll
            for (int c = 0; c < 4; c++) {
                int t = t0 + tx*4 + c;
                float v = (t <= j) ? acc[i][c] * 0.125f : -1e30f;
                acc[i][c] = v;
                mx = fmaxf(mx, v);
            }
#pragma unroll
            for (int off = 8; off; off >>= 1)
                mx = fmaxf(mx, __shfl_xor_sync(0xffffffffu, mx, off, 16));
            float mnew = fmaxf(mrow[i], mx);
            float corr = __expf(mrow[i] - mnew);
            float ss = 0.f;
#pragma unroll
            for (int c = 0; c < 4; c++) {
                float p = __expf(acc[i][c] - mnew);
                acc[i][c] = p;
                ss += p;
            }
#pragma unroll
            for (int off = 8; off; off >>= 1)
                ss += __shfl_xor_sync(0xffffffffu, ss, off, 16);
            lrow[i] = lrow[i] * corr + ss;
            mrow[i] = mnew;
            u64 corr2 = dup2(corr);
            oacc2[i][0] = fmul2(oacc2[i][0], corr2);
            oacc2[i][1] = fmul2(oacc2[i][1], corr2);
        }
        __syncthreads();   // (c)

        // store p transposed: ps[t][j] (inside rp), load V -> kv[t][d]
        float* ps = rp;
#pragma unroll
        for (int c = 0; c < 4; c++) {
            float4 pv = make_float4(acc[0][c], acc[1][c], acc[2][c], acc[3][c]);
            *(float4*)(ps + (tx*4 + c)*68 + ty*4) = pv;
        }
        for (int f = tid; f < 1024; f += 256) {
            int t = f >> 4, d4 = (f & 15) << 2;
            float4 vv = *(const float4*)(Vbase + (size_t)(t0 + t)*DHc + d4);
            *(float4*)(kv + t*68 + d4) = vv;
        }
        __syncthreads();   // (d)

        // O += P @ V  (f32x2, pairs along DH cols)
#pragma unroll 8
        for (int t = 0; t < 64; t++) {
            ulonglong2 vv2 = *(ulonglong2*)(kv + t*68 + tx*4);
            float4 p4 = *(float4*)(ps + t*68 + ty*4);
            u64 pa0 = dup2(p4.x), pa1 = dup2(p4.y), pa2v = dup2(p4.z), pa3 = dup2(p4.w);
            oacc2[0][0] = ffma2(pa0,  vv2.x, oacc2[0][0]);
            oacc2[0][1] = ffma2(pa0,  vv2.y, oacc2[0][1]);
            oacc2[1][0] = ffma2(pa1,  vv2.x, oacc2[1][0]);
            oacc2[1][1] = ffma2(pa1,  vv2.y, oacc2[1][1]);
            oacc2[2][0] = ffma2(pa2v, vv2.x, oacc2[2][0]);
            oacc2[2][1] = ffma2(pa2v, vv2.y, oacc2[2][1]);
            oacc2[3][0] = ffma2(pa3,  vv2.x, oacc2[3][0]);
            oacc2[3][1] = ffma2(pa3,  vv2.y, oacc2[3][1]);
        }
    }

    if (!split) {
        // direct epilogue: ctx[b][j][h*64 + dc]
        const int b = bh >> 3;
#pragma unroll
        for (int i = 0; i < 4; i++) {
            float inv = 1.f / lrow[i];
            float2 u0 = unpk2(oacc2[i][0]), u1 = unpk2(oacc2[i][1]);
            float4 o = make_float4(u0.x*inv, u0.y*inv, u1.x*inv, u1.y*inv);
            *(float4*)&g_ctx[((size_t)(b*Sc + j0 + ty*4 + i)) * Dc + h*DHc + tx*4] = o;
        }
    } else {
        // write unnormalized partial (O, m, l)
        float* P = g_part + (size_t)(((bh*8 + (jt - 8)) << 1) + ci) * 64 * 68;
#pragma unroll
        for (int i = 0; i < 4; i++) {
            const int r = ty*4 + i;
            float2 u0 = unpk2(oacc2[i][0]), u1 = unpk2(oacc2[i][1]);
            *(float4*)&P[r*68 + tx*4] = make_float4(u0.x, u0.y, u1.x, u1.y);
            if (tx == 0) {
                P[r*68 + 64] = mrow[i];
                P[r*68 + 65] = lrow[i];
            }
        }
    }
}

// ============================================================
// Combine split-K partials: one CTA per (bh, split j-tile).
// ============================================================
__global__ __launch_bounds__(256) void attn_combine() {
    const int bh = blockIdx.x >> 3;
    const int jt = 8 + (blockIdx.x & 7);
    const int j0 = jt << 6;
    const int b = bh >> 3, h = bh & 7;

    const float* PA = g_part + (size_t)(((bh*8 + (jt - 8)) << 1) + 0) * 64 * 68;
    const float* PB = g_part + (size_t)(((bh*8 + (jt - 8)) << 1) + 1) * 64 * 68;

    const int r  = threadIdx.x >> 2;          // 0..63 row
    const int c0 = (threadIdx.x & 3) << 4;    // 0,16,32,48

    const float mA = PA[r*68 + 64], lA = PA[r*68 + 65];
    const float mB = PB[r*68 + 64], lB = PB[r*68 + 65];
    const float m  = fmaxf(mA, mB);
    const float wA = __expf(mA - m), wB = __expf(mB - m);
    const float inv = 1.f / (wA*lA + wB*lB);
    const float fA = wA * inv, fB = wB * inv;

    float* dst = &g_ctx[((size_t)(b*Sc + j0 + r)) * Dc + h*DHc];
#pragma unroll
    for (int c = 0; c < 16; c += 4) {
        float4 a = *(const float4*)&PA[r*68 + c0 + c];
        float4 bb = *(const float4*)&PB[r*68 + c0 + c];
        float4 o = make_float4(fA*a.x + fB*bb.x, fA*a.y + fB*bb.y,
                               fA*a.z + fB*bb.z, fA*a.w + fB*bb.w);
        *(float4*)&dst[c0 + c] = o;
    }
}

// ============================================================
extern "C" void kernel_launch(void* const* d_in, const int* in_sizes, int n_in,
                              void* d_out, int out_size) {
    (void)in_sizes; (void)n_in; (void)out_size;
    const float* queries = (const float*)d_in[0];
    const float* keysp   = (const float*)d_in[1];
    const float* valuesp = (const float*)d_in[2];
    // d_in[3] = mask (causal; applied analytically)
    const float* Wq  = (const float*)d_in[4];
    const float* Wk  = (const float*)d_in[5];
    const float* Wv  = (const float*)d_in[6];
    const float* Wo  = (const float*)d_in[7];
    const float* rel = (const float*)d_in[8];
    float* out = (float*)d_out;

    float *pQ, *pK, *pV;
    cudaGetSymbolAddress((void**)&pQ, g_Q);
    cudaGetSymbolAddress((void**)&pK, g_K);
    cudaGetSymbolAddress((void**)&pV, g_V);

    // 1) transpose activations -> g_AT  [3][512][4096]
    transpose3<<<dim3(Dc/32, Mt/32, 3), 256>>>(queries, keysp, valuesp);

    // 2) fused QKV projections (cp.async pipelined GEMM)
    proj3<<<dim3(Dc/64, Mt/128, 3), 256>>>(Wq, Wk, Wv, pQ, pK, pV);

    // 3) attention, split-K chunks (24 per bh, longest-first)
    const int smem = (2*64*68 + 64*128) * (int)sizeof(float);   // 67584 B -> 3 CTAs/SM
    cudaFuncSetAttribute(attn_kernel, cudaFuncAttributeMaxDynamicSharedMemorySize, smem);
    attn_kernel<<<dim3(24, Bc*Hc), 256, smem>>>(rel);

    // 3b) merge partials for split j-tiles
    attn_combine<<<Bc*Hc*8, 256>>>();

    // 4) transpose ctx -> g_CT, then output projection
    transpose1<<<dim3(Dc/32, Mt/32), 256>>>();
    gemm_out<<<dim3(Dc/64, Mt/128), 256>>>(Wo, out);
}

// round 15
// speedup vs baseline: 1.9279x; 1.1231x over previous
#include <cuda_runtime.h>

#define Bc 4
#define Sc 1024
#define Dc 512
#define Hc 8
#define DHc 64
#define Mt (Bc*Sc)          // 4096 rows of activations

typedef unsigned long long u64;

// ---- f32x2 packed-math helpers (FFMA2 path: ptxas only emits via PTX) ----
__device__ __forceinline__ u64 ffma2(u64 a, u64 b, u64 c) {
    u64 d;
    asm("fma.rn.f32x2 %0, %1, %2, %3;" : "=l"(d) : "l"(a), "l"(b), "l"(c));
    return d;
}
__device__ __forceinline__ u64 fmul2(u64 a, u64 b) {
    u64 d;
    asm("mul.rn.f32x2 %0, %1, %2;" : "=l"(d) : "l"(a), "l"(b));
    return d;
}
__device__ __forceinline__ u64 pack2(float lo, float hi) {
    u64 d;
    asm("mov.b64 %0, {%1, %2};" : "=l"(d)
        : "r"(__float_as_uint(lo)), "r"(__float_as_uint(hi)));
    return d;
}
__device__ __forceinline__ u64 dup2(float x) { return pack2(x, x); }
__device__ __forceinline__ float2 unpk2(u64 v) {
    unsigned lo, hi;
    asm("mov.b64 {%0, %1}, %2;" : "=r"(lo), "=r"(hi) : "l"(v));
    return make_float2(__uint_as_float(lo), __uint_as_float(hi));
}

// ---- cp.async helpers ----
__device__ __forceinline__ void cpa16(unsigned dst, const void* src) {
    asm volatile("cp.async.ca.shared.global [%0], [%1], 16;" :: "r"(dst), "l"(src));
}
__device__ __forceinline__ void cpa_commit() {
    asm volatile("cp.async.commit_group;");
}
__device__ __forceinline__ void cpa_wait0() {
    asm volatile("cp.async.wait_group 0;" ::: "memory");
}

// ---- scratch (no allocations allowed) ----
__device__ float g_Q[Bc*Hc*Sc*DHc];    // [B,H,S,DH]
__device__ float g_K[Bc*Hc*Sc*DHc];
__device__ float g_V[Bc*Hc*Sc*DHc];
__device__ float g_ctx[Bc*Sc*Dc];      // [B,S,D]
__device__ float g_AT[3*Dc*Mt];        // transposed activations [3][512][4096]
__device__ float g_CT[Dc*Mt];          // transposed ctx [512][4096]
// split-K attention partials: [32 bh][8 split j-tiles][2 chunks][64 rows][68]
__device__ float g_part[32*8*2*64*68];
__device__ int   g_ctr;                // work-queue counter (reset in transpose3)

// Work-item table, rank-major (24 ranks per bh), sorted longest-first.
// rank -> (jt, tbeg, tend). Splits use half=(nt+1)>>1 boundaries (combine relies on it).
__constant__ signed char c_jt[24] = {15,15,14, 7,14,13,13,12, 6,12,11,11,10, 5,10, 9, 9, 8, 4, 8, 3, 2, 1, 0};
__constant__ signed char c_tb[24] = { 0, 8, 0, 0, 8, 0, 7, 0, 0, 7, 0, 6, 0, 0, 6, 0, 5, 0, 0, 5, 0, 0, 0, 0};
__constant__ signed char c_te[24] = { 8,16, 8, 8,15, 7,14, 7, 7,13, 6,12, 6, 6,11, 5,10, 5, 5, 9, 4, 3, 2, 1};
#define N_ITEMS (24*32)

// ============================================================
// Tiled transpose: in[M=4096][N=512] -> out[N=512][M=4096]
// ============================================================
__device__ __forceinline__ void transpose_body(const float* __restrict__ in,
                                               float* __restrict__ out) {
    __shared__ float t[32][33];
    const int lx = threadIdx.x & 31, ly = threadIdx.x >> 5;   // 32 x 8
    const int bx = blockIdx.x << 5;
    const int by = blockIdx.y << 5;
#pragma unroll
    for (int u = 0; u < 4; u++)
        t[ly + u*8][lx] = in[(size_t)(by + ly + u*8) * Dc + bx + lx];
    __syncthreads();
#pragma unroll
    for (int u = 0; u < 4; u++)
        out[(size_t)(bx + ly + u*8) * Mt + by + lx] = t[lx][ly + u*8];
}

__global__ __launch_bounds__(256) void transpose3(const float* __restrict__ q,
                                                  const float* __restrict__ k,
                                                  const float* __restrict__ v) {
    if (blockIdx.x == 0 && blockIdx.y == 0 && blockIdx.z == 0 && threadIdx.x == 0)
        g_ctr = 0;   // reset attn work queue (runs before attn in-stream)
    const int z = blockIdx.z;
    const float* in = (z == 0) ? q : (z == 1) ? k : v;
    transpose_body(in, g_AT + (size_t)z * Dc * Mt);
}

__global__ __launch_bounds__(256) void transpose1() {
    transpose_body(g_ctx, g_CT);
}

// ============================================================
// GEMM (cp.async pipelined): out = A[M,512] @ W[512,512],
// A supplied TRANSPOSED as AT[512][4096].
// ============================================================
__device__ __forceinline__ void gemm_ca(const float* __restrict__ AT,
                                        const float* __restrict__ W,
                                        float* __restrict__ out,
                                        int headsplit) {
    __shared__ float As[2][16][132];
    __shared__ float Bs[2][16][68];
    const int tid = threadIdx.x;
    const int tx = tid & 15;
    const int ty = tid >> 4;
    const int m0 = blockIdx.y << 7, n0 = blockIdx.x << 6;

    const int arow0 = tid >> 5;
    const int acol0 = (tid & 31) << 2;
    const int brow = tid >> 4;
    const int bcol = (tid & 15) << 2;

    const unsigned aB0 = (unsigned)__cvta_generic_to_shared(&As[0][0][0]);
    const unsigned aB1 = (unsigned)__cvta_generic_to_shared(&As[1][0][0]);
    const unsigned bB0 = (unsigned)__cvta_generic_to_shared(&Bs[0][0][0]);
    const unsigned bB1 = (unsigned)__cvta_generic_to_shared(&Bs[1][0][0]);

    const float* Abase = AT + m0 + (size_t)arow0 * Mt + acol0;
    const float* Wbase = W + n0 + (size_t)brow * Dc + bcol;

    u64 acc[4][4];
#pragma unroll
    for (int i = 0; i < 4; i++)
#pragma unroll
        for (int j = 0; j < 4; j++) acc[i][j] = 0ull;

    auto issue = [&](int buf, int k0) {
        const unsigned aB = buf ? aB1 : aB0;
        const unsigned bB = buf ? bB1 : bB0;
        cpa16(aB + (unsigned)(arow0 * 132 + acol0) * 4,
              Abase + (size_t)k0 * Mt);
        cpa16(aB + (unsigned)((arow0 + 8) * 132 + acol0) * 4,
              Abase + (size_t)(k0 + 8) * Mt);
        cpa16(bB + (unsigned)(brow * 68 + bcol) * 4,
              Wbase + (size_t)k0 * Dc);
    };

    issue(0, 0);
    cpa_commit();

    int buf = 0;
#pragma unroll 1
    for (int k0 = 0; k0 < 512; k0 += 16) {
        cpa_wait0();
        __syncthreads();
        if (k0 + 16 < 512) {
            issue(buf ^ 1, k0 + 16);
            cpa_commit();
        }
#pragma unroll
        for (int kk = 0; kk < 16; kk++) {
            ulonglong2 a01 = *(ulonglong2*)&As[buf][kk][ty*8];
            ulonglong2 a23 = *(ulonglong2*)&As[buf][kk][ty*8 + 4];
            float4 bv = *(float4*)&Bs[buf][kk][tx*4];
            u64 a2[4] = { a01.x, a01.y, a23.x, a23.y };
            u64 b2[4] = { dup2(bv.x), dup2(bv.y), dup2(bv.z), dup2(bv.w) };
#pragma unroll
            for (int i = 0; i < 4; i++)
#pragma unroll
                for (int j = 0; j < 4; j++)
                    acc[i][j] = ffma2(a2[i], b2[j], acc[i][j]);
        }
        buf ^= 1;
    }

    const int n = n0 + tx*4;
    if (headsplit) {
        const int hh = n >> 6;
        const int nc = n & 63;
#pragma unroll
        for (int i = 0; i < 4; i++) {
            float2 c0 = unpk2(acc[i][0]), c1 = unpk2(acc[i][1]);
            float2 c2 = unpk2(acc[i][2]), c3 = unpk2(acc[i][3]);
            int m = m0 + ty*8 + 2*i;
            int bb = m >> 10, s = m & 1023;
            *(float4*)&out[((size_t)(bb*Hc + hh) * Sc + s) * DHc + nc] =
                make_float4(c0.x, c1.x, c2.x, c3.x);
            int m2 = m + 1, bb2 = m2 >> 10, s2 = m2 & 1023;
            *(float4*)&out[((size_t)(bb2*Hc + hh) * Sc + s2) * DHc + nc] =
                make_float4(c0.y, c1.y, c2.y, c3.y);
        }
    } else {
#pragma unroll
        for (int i = 0; i < 4; i++) {
            float2 c0 = unpk2(acc[i][0]), c1 = unpk2(acc[i][1]);
            float2 c2 = unpk2(acc[i][2]), c3 = unpk2(acc[i][3]);
            int m = m0 + ty*8 + 2*i;
            *(float4*)&out[(size_t)m * 512 + n] = make_float4(c0.x, c1.x, c2.x, c3.x);
            *(float4*)&out[(size_t)(m+1) * 512 + n] = make_float4(c0.y, c1.y, c2.y, c3.y);
        }
    }
}

__global__ __launch_bounds__(256, 3) void proj3(const float* __restrict__ W0,
                                                const float* __restrict__ W1,
                                                const float* __restrict__ W2,
                                                float* __restrict__ O0,
                                                float* __restrict__ O1,
                                                float* __restrict__ O2) {
    const int z = blockIdx.z;
    const float* AT = g_AT + (size_t)z * Dc * Mt;
    const float* W = (z == 0) ? W0 : (z == 1) ? W1 : W2;
    float*       O = (z == 0) ? O0 : (z == 1) ? O1 : O2;
    gemm_ca(AT, W, O, 1);
}

__global__ __launch_bounds__(256, 3) void gemm_out(const float* __restrict__ W,
                                                   float* __restrict__ out) {
    gemm_ca(g_CT, W, out, 0);
}

// ============================================================
// Persistent work-stealing attention. Each worker CTA pulls
// (bh, rank) items (longest-first LPT order) from g_ctr and runs
// the same chunk math as R14: split j-tiles (jt>=8) write
// unnormalized partials, singles write ctx directly.
// ============================================================
__global__ __launch_bounds__(256, 3) void attn_kernel(const float* __restrict__ Rel) {
    extern __shared__ float sm[];
    float* qs = sm;                 // [d][j]  64x68
    float* kv = qs + 64*68;         // QK: K as [d][t] ; PV: V as [t][d]
    float* rp = kv + 64*68;         // QK: R as [d][cc] 64x128 ; PV: ps as [t][j]
    int*   sm_item = (int*)(rp + 64*128);   // 1-int broadcast slot

    const int tid = threadIdx.x;
    const int tx = tid & 15, ty = tid >> 4;
    const int base0 = 60 + 4*tx - 4*ty;   // in [0,120], mult of 4

    for (;;) {
        __syncthreads();              // prior item fully done; slot reusable
        if (tid == 0) *sm_item = atomicAdd(&g_ctr, 1);
        __syncthreads();
        const int item = *sm_item;
        if (item >= N_ITEMS) break;

        const int bh   = item & 31;
        const int rank = item >> 5;
        const int jt   = c_jt[rank];
        const int tbeg = c_tb[rank], tend = c_te[rank];
        const bool split = (jt >= 8);
        const int ci   = tbeg ? 1 : 0;
        const int j0   = jt << 6;
        const int h    = bh & (Hc-1);

        const float* Qp    = g_Q + ((size_t)bh * Sc + j0) * DHc;
        const float* Kbase = g_K + (size_t)bh * Sc * DHc;
        const float* Vbase = g_V + (size_t)bh * Sc * DHc;
        const float* Rp    = Rel + (size_t)h * DHc * Sc;

        for (int f = tid; f < 1024; f += 256) {
            int j = f >> 4, d4 = (f & 15) << 2;
            float4 v = *(const float4*)(Qp + j*DHc + d4);
            qs[(d4+0)*68 + j] = v.x; qs[(d4+1)*68 + j] = v.y;
            qs[(d4+2)*68 + j] = v.z; qs[(d4+3)*68 + j] = v.w;
        }

        float mrow[4] = {-1e30f, -1e30f, -1e30f, -1e30f};
        float lrow[4] = {0.f, 0.f, 0.f, 0.f};
        u64 oacc2[4][2];
#pragma unroll
        for (int i = 0; i < 4; i++) { oacc2[i][0] = 0ull; oacc2[i][1] = 0ull; }

        for (int it = tbeg; it < tend; it++) {
            const int t0 = it << 6;
            __syncthreads();   // (a) qs visible; kv/rp free

            for (int f = tid; f < 1024; f += 256) {
                int t = f >> 4, d4 = (f & 15) << 2;
                float4 k4 = *(const float4*)(Kbase + (size_t)(t0 + t)*DHc + d4);
                kv[(d4+0)*68 + t] = k4.x; kv[(d4+1)*68 + t] = k4.y;
                kv[(d4+2)*68 + t] = k4.z; kv[(d4+3)*68 + t] = k4.w;
            }
            const int cmin = Sc - 64 - j0 + t0;   // >= 0, multiple of 4
            for (int f = tid; f < 64*32; f += 256) {
                int d = f >> 5, cc4 = (f & 31) << 2;
                int col = cmin + cc4;
                float4 rv4 = (col < Sc) ? *(const float4*)(Rp + (size_t)d*Sc + col)
                                        : make_float4(0.f, 0.f, 0.f, 0.f);
                *(float4*)(rp + d*128 + cc4) = rv4;
            }
            __syncthreads();   // (b)

            // s[j][t] = q.k + q.R[:, S-1-j+t]  -- f32x2, pairs along t
            u64 acc2[4][2];
#pragma unroll
            for (int i = 0; i < 4; i++) { acc2[i][0] = 0ull; acc2[i][1] = 0ull; }
#pragma unroll 8
            for (int d = 0; d < 64; d++) {
                float4 qv = *(float4*)(qs + d*68 + ty*4);
                ulonglong2 kk2 = *(ulonglong2*)(kv + d*68 + tx*4);
                float4 r0 = *(float4*)(rp + d*128 + base0);
                float4 r1 = *(float4*)(rp + d*128 + base0 + 4);
                u64 qa2[4] = { dup2(qv.x), dup2(qv.y), dup2(qv.z), dup2(qv.w) };
                u64 e0 = pack2(r0.x, r0.y), e1 = pack2(r0.z, r0.w), e2 = pack2(r1.x, r1.y);
                u64 o1 = pack2(r0.y, r0.z), o3 = pack2(r0.w, r1.x), o5 = pack2(r1.y, r1.z);
                u64 rb00 = o3, rb01 = o5;   // i=0
                u64 rb10 = e1, rb11 = e2;   // i=1
                u64 rb20 = o1, rb21 = o3;   // i=2
                u64 rb30 = e0, rb31 = e1;   // i=3
                acc2[0][0] = ffma2(qa2[0], kk2.x, acc2[0][0]);
                acc2[0][1] = ffma2(qa2[0], kk2.y, acc2[0][1]);
                acc2[0][0] = ffma2(qa2[0], rb00,  acc2[0][0]);
                acc2[0][1] = ffma2(qa2[0], rb01,  acc2[0][1]);
                acc2[1][0] = ffma2(qa2[1], kk2.x, acc2[1][0]);
                acc2[1][1] = ffma2(qa2[1], kk2.y, acc2[1][1]);
                acc2[1][0] = ffma2(qa2[1], rb10,  acc2[1][0]);
                acc2[1][1] = ffma2(qa2[1], rb11,  acc2[1][1]);
                acc2[2][0] = ffma2(qa2[2], kk2.x, acc2[2][0]);
                acc2[2][1] = ffma2(qa2[2], kk2.y, acc2[2][1]);
                acc2[2][0] = ffma2(qa2[2], rb20,  acc2[2][0]);
                acc2[2][1] = ffma2(qa2[2], rb21,  acc2[2][1]);
                acc2[3][0] = ffma2(qa2[3], kk2.x, acc2[3][0]);
                acc2[3][1] = ffma2(qa2[3], kk2.y, acc2[3][1]);
                acc2[3][0] = ffma2(qa2[3], rb30,  acc2[3][0]);
                acc2[3][1] = ffma2(qa2[3], rb31,  acc2[3][1]);
            }

            float acc[4][4];
#pragma unroll
            for (int i = 0; i < 4; i++) {
                float2 u0 = unpk2(acc2[i][0]), u1 = unpk2(acc2[i][1]);
                acc[i][0] = u0.x; acc[i][1] = u0.y; acc[i][2] = u1.x; acc[i][3] = u1.y;
            }

            // online softmax (scale AFTER bias+mask, matching reference)
#pragma unroll
            for (int i = 0; i < 4; i++) {
                const int j = j0 + ty*4 + i;
                float mx = -1e30f;
#pragma unroll
                for (int c = 0; c < 4; c++) {
                    int t = t0 + tx*4 + c;
                    float v = (t <= j) ? acc[i][c] * 0.125f : -1e30f;
                    acc[i][c] = v;
                    mx = fmaxf(mx, v);
                }
#pragma unroll
                for (int off = 8; off; off >>= 1)
                    mx = fmaxf(mx, __shfl_xor_sync(0xffffffffu, mx, off, 16));
                float mnew = fmaxf(mrow[i], mx);
                float corr = __expf(mrow[i] - mnew);
                float ss = 0.f;
#pragma unroll
                for (int c = 0; c < 4; c++) {
                    float p = __expf(acc[i][c] - mnew);
                    acc[i][c] = p;
                    ss += p;
                }
#pragma unroll
                for (int off = 8; off; off >>= 1)
                    ss += __shfl_xor_sync(0xffffffffu, ss, off, 16);
                lrow[i] = lrow[i] * corr + ss;
                mrow[i] = mnew;
                u64 corr2 = dup2(corr);
                oacc2[i][0] = fmul2(oacc2[i][0], corr2);
                oacc2[i][1] = fmul2(oacc2[i][1], corr2);
            }
            __syncthreads();   // (c)

            // store p transposed: ps[t][j] (inside rp), load V -> kv[t][d]
            float* ps = rp;
#pragma unroll
            for (int c = 0; c < 4; c++) {
                float4 pv = make_float4(acc[0][c], acc[1][c], acc[2][c], acc[3][c]);
                *(float4*)(ps + (tx*4 + c)*68 + ty*4) = pv;
            }
            for (int f = tid; f < 1024; f += 256) {
                int t = f >> 4, d4 = (f & 15) << 2;
                float4 vv = *(const float4*)(Vbase + (size_t)(t0 + t)*DHc + d4);
                *(float4*)(kv + t*68 + d4) = vv;
            }
            __syncthreads();   // (d)

            // O += P @ V  (f32x2, pairs along DH cols)
#pragma unroll 8
            for (int t = 0; t < 64; t++) {
                ulonglong2 vv2 = *(ulonglong2*)(kv + t*68 + tx*4);
                float4 p4 = *(float4*)(ps + t*68 + ty*4);
                u64 pa0 = dup2(p4.x), pa1 = dup2(p4.y), pa2v = dup2(p4.z), pa3 = dup2(p4.w);
                oacc2[0][0] = ffma2(pa0,  vv2.x, oacc2[0][0]);
                oacc2[0][1] = ffma2(pa0,  vv2.y, oacc2[0][1]);
                oacc2[1][0] = ffma2(pa1,  vv2.x, oacc2[1][0]);
                oacc2[1][1] = ffma2(pa1,  vv2.y, oacc2[1][1]);
                oacc2[2][0] = ffma2(pa2v, vv2.x, oacc2[2][0]);
                oacc2[2][1] = ffma2(pa2v, vv2.y, oacc2[2][1]);
                oacc2[3][0] = ffma2(pa3,  vv2.x, oacc2[3][0]);
                oacc2[3][1] = ffma2(pa3,  vv2.y, oacc2[3][1]);
            }
        }

        if (!split) {
            const int b = bh >> 3;
#pragma unroll
            for (int i = 0; i < 4; i++) {
                float inv = 1.f / lrow[i];
                float2 u0 = unpk2(oacc2[i][0]), u1 = unpk2(oacc2[i][1]);
                float4 o = make_float4(u0.x*inv, u0.y*inv, u1.x*inv, u1.y*inv);
                *(float4*)&g_ctx[((size_t)(b*Sc + j0 + ty*4 + i)) * Dc + h*DHc + tx*4] = o;
            }
        } else {
            float* P = g_part + (size_t)(((bh*8 + (jt - 8)) << 1) + ci) * 64 * 68;
#pragma unroll
            for (int i = 0; i < 4; i++) {
                const int r = ty*4 + i;
                float2 u0 = unpk2(oacc2[i][0]), u1 = unpk2(oacc2[i][1]);
                *(float4*)&P[r*68 + tx*4] = make_float4(u0.x, u0.y, u1.x, u1.y);
                if (tx == 0) {
                    P[r*68 + 64] = mrow[i];
                    P[r*68 + 65] = lrow[i];
                }
            }
        }
    }
}

// ============================================================
// Combine split-K partials: one CTA per (bh, split j-tile).
// ============================================================
__global__ __launch_bounds__(256) void attn_combine() {
    const int bh = blockIdx.x >> 3;
    const int jt = 8 + (blockIdx.x & 7);
    const int j0 = jt << 6;
    const int b = bh >> 3, h = bh & 7;

    const float* PA = g_part + (size_t)(((bh*8 + (jt - 8)) << 1) + 0) * 64 * 68;
    const float* PB = g_part + (size_t)(((bh*8 + (jt - 8)) << 1) + 1) * 64 * 68;

    const int r  = threadIdx.x >> 2;
    const int c0 = (threadIdx.x & 3) << 4;

    const float mA = PA[r*68 + 64], lA = PA[r*68 + 65];
    const float mB = PB[r*68 + 64], lB = PB[r*68 + 65];
    const float m  = fmaxf(mA, mB);
    const float wA = __expf(mA - m), wB = __expf(mB - m);
    const float inv = 1.f / (wA*lA + wB*lB);
    const float fA = wA * inv, fB = wB * inv;

    float* dst = &g_ctx[((size_t)(b*Sc + j0 + r)) * Dc + h*DHc];
#pragma unroll
    for (int c = 0; c < 16; c += 4) {
        float4 a = *(const float4*)&PA[r*68 + c0 + c];
        float4 bb = *(const float4*)&PB[r*68 + c0 + c];
        float4 o = make_float4(fA*a.x + fB*bb.x, fA*a.y + fB*bb.y,
                               fA*a.z + fB*bb.z, fA*a.w + fB*bb.w);
        *(float4*)&dst[c0 + c] = o;
    }
}

// ============================================================
extern "C" void kernel_launch(void* const* d_in, const int* in_sizes, int n_in,
                              void* d_out, int out_size) {
    (void)in_sizes; (void)n_in; (void)out_size;
    const float* queries = (const float*)d_in[0];
    const float* keysp   = (const float*)d_in[1];
    const float* valuesp = (const float*)d_in[2];
    // d_in[3] = mask (causal; applied analytically)
    const float* Wq  = (const float*)d_in[4];
    const float* Wk  = (const float*)d_in[5];
    const float* Wv  = (const float*)d_in[6];
    const float* Wo  = (const float*)d_in[7];
    const float* rel = (const float*)d_in[8];
    float* out = (float*)d_out;

    float *pQ, *pK, *pV;
    cudaGetSymbolAddress((void**)&pQ, g_Q);
    cudaGetSymbolAddress((void**)&pK, g_K);
    cudaGetSymbolAddress((void**)&pV, g_V);

    // 1) transpose activations -> g_AT (also resets attn work queue)
    transpose3<<<dim3(Dc/32, Mt/32, 3), 256>>>(queries, keysp, valuesp);

    // 2) fused QKV projections (cp.async pipelined GEMM)
    proj3<<<dim3(Dc/64, Mt/128, 3), 256>>>(Wq, Wk, Wv, pQ, pK, pV);

    // 3) attention: persistent work-stealing workers (152 SM * 3)
    const int smem = (2*64*68 + 64*128 + 4) * (int)sizeof(float);
    cudaFuncSetAttribute(attn_kernel, cudaFuncAttributeMaxDynamicSharedMemorySize, smem);
    attn_kernel<<<456, 256, smem>>>(rel);

    // 3b) merge partials for split j-tiles
    attn_combine<<<Bc*Hc*8, 256>>>();

    // 4) transpose ctx -> g_CT, then output projection
    transpose1<<<dim3(Dc/32, Mt/32), 256>>>();
    gemm_out<<<dim3(Dc/64, Mt/128), 256>>>(Wo, out);
}